// round 1
// baseline (speedup 1.0000x reference)
#include <cuda_runtime.h>
#include <cuda_bf16.h>
#include <stdint.h>

// ---------------------------------------------------------------------------
// ConvGraph: out = spmm(A_coo, x @ W)
//   x: [M, 256] f32, W: [256, 128] f32
//   edges: src[E], dst[E] i32, weight[E] f32
//   out[d, :] = sum_{e: dst_e == d} w_e * (x @ W)[src_e, :]
// ---------------------------------------------------------------------------

#define D_IN   256
#define D_OUT  128
#define MAX_M  100000

// scratch for h = x @ W  (51.2 MB, static device array per harness rules)
__device__ float g_h[MAX_M * D_OUT];

// ---------------------------------------------------------------------------
// Kernel 1: zero d_out (it is poisoned to 0xAA before timing)
// ---------------------------------------------------------------------------
__global__ void zero_kernel(float4* out, int n4) {
    int i = blockIdx.x * blockDim.x + threadIdx.x;
    int stride = gridDim.x * blockDim.x;
    for (; i < n4; i += stride)
        out[i] = make_float4(0.f, 0.f, 0.f, 0.f);
}

// ---------------------------------------------------------------------------
// Kernel 2: SGEMM  h[M,128] = x[M,256] @ W[256,128]
// Tile: 128 rows x 128 cols per block, K-chunks of 8. 256 threads,
// each thread computes an 8x8 register micro-tile.
// ---------------------------------------------------------------------------
__global__ __launch_bounds__(256, 2)
void gemm_kernel(const float* __restrict__ x,
                 const float* __restrict__ W,
                 float* __restrict__ h,
                 int M) {
    __shared__ float As[8][128];   // [k][row]
    __shared__ float Bs[8][128];   // [k][col]

    const int row0 = blockIdx.x * 128;
    const int tid  = threadIdx.x;
    const int tx   = tid & 15;        // 0..15 -> col group
    const int ty   = tid >> 4;        // 0..15 -> row group

    float acc[8][8];
#pragma unroll
    for (int i = 0; i < 8; i++)
#pragma unroll
        for (int j = 0; j < 8; j++)
            acc[i][j] = 0.f;

    // A-load mapping: thread t loads float4 at (row = t/2, kc = (t%2)*4)
    const int a_r  = tid >> 1;
    const int a_c4 = (tid & 1) * 4;
    // B-load mapping: thread t loads float4 at (k = t/32, col = (t%32)*4)
    const int b_k  = tid >> 5;
    const int b_c4 = (tid & 31) * 4;

    const bool a_row_ok = (row0 + a_r) < M;

    for (int k0 = 0; k0 < D_IN; k0 += 8) {
        // load A tile 128x8 (transposed into As[k][row])
        float4 av = make_float4(0.f, 0.f, 0.f, 0.f);
        if (a_row_ok)
            av = *reinterpret_cast<const float4*>(
                     &x[(size_t)(row0 + a_r) * D_IN + k0 + a_c4]);
        As[a_c4 + 0][a_r] = av.x;
        As[a_c4 + 1][a_r] = av.y;
        As[a_c4 + 2][a_r] = av.z;
        As[a_c4 + 3][a_r] = av.w;

        // load B tile 8x128
        float4 bv = *reinterpret_cast<const float4*>(
                        &W[(size_t)(k0 + b_k) * D_OUT + b_c4]);
        *reinterpret_cast<float4*>(&Bs[b_k][b_c4]) = bv;

        __syncthreads();

#pragma unroll
        for (int k = 0; k < 8; k++) {
            float a[8], b[8];
#pragma unroll
            for (int i = 0; i < 8; i++) a[i] = As[k][ty * 8 + i];
            // two LDS.128 for b
            float4 b0 = *reinterpret_cast<const float4*>(&Bs[k][tx * 8]);
            float4 b1 = *reinterpret_cast<const float4*>(&Bs[k][tx * 8 + 4]);
            b[0]=b0.x; b[1]=b0.y; b[2]=b0.z; b[3]=b0.w;
            b[4]=b1.x; b[5]=b1.y; b[6]=b1.z; b[7]=b1.w;
#pragma unroll
            for (int i = 0; i < 8; i++)
#pragma unroll
                for (int j = 0; j < 8; j++)
                    acc[i][j] = fmaf(a[i], b[j], acc[i][j]);
        }
        __syncthreads();
    }

    // store 8x8 micro-tile
#pragma unroll
    for (int i = 0; i < 8; i++) {
        int r = row0 + ty * 8 + i;
        if (r < M) {
            float4 v0 = make_float4(acc[i][0], acc[i][1], acc[i][2], acc[i][3]);
            float4 v1 = make_float4(acc[i][4], acc[i][5], acc[i][6], acc[i][7]);
            *reinterpret_cast<float4*>(&h[(size_t)r * D_OUT + tx * 8])     = v0;
            *reinterpret_cast<float4*>(&h[(size_t)r * D_OUT + tx * 8 + 4]) = v1;
        }
    }
}

// ---------------------------------------------------------------------------
// Kernel 3: edge scatter. One warp per edge; each lane handles one float4
// (32 lanes * 16B = 512B = one 128-float row). 4 scalar atomicAdds per lane
// (compiled to RED.E.ADD.F32 since return value is unused).
// ---------------------------------------------------------------------------
__global__ __launch_bounds__(256)
void scatter_kernel(const float* __restrict__ h,
                    const int*   __restrict__ src,
                    const int*   __restrict__ dst,
                    const float* __restrict__ ew,
                    float*       __restrict__ out,
                    int E) {
    const int warp_id = (blockIdx.x * blockDim.x + threadIdx.x) >> 5;
    const int lane    = threadIdx.x & 31;
    if (warp_id >= E) return;

    int   s, d;
    float w;
    if (lane == 0) {
        s = src[warp_id];
        d = dst[warp_id];
        w = ew[warp_id];
    }
    s = __shfl_sync(0xffffffffu, s, 0);
    d = __shfl_sync(0xffffffffu, d, 0);
    w = __shfl_sync(0xffffffffu, w, 0);

    const float4 v = *reinterpret_cast<const float4*>(
                         &h[(size_t)s * D_OUT + lane * 4]);

    float* o = &out[(size_t)d * D_OUT + lane * 4];
    atomicAdd(o + 0, w * v.x);
    atomicAdd(o + 1, w * v.y);
    atomicAdd(o + 2, w * v.z);
    atomicAdd(o + 3, w * v.w);
}

// ---------------------------------------------------------------------------
extern "C" void kernel_launch(void* const* d_in, const int* in_sizes, int n_in,
                              void* d_out, int out_size) {
    const float* x   = (const float*)d_in[0];
    const float* W   = (const float*)d_in[1];
    const int*   src = (const int*)  d_in[2];
    const int*   dst = (const int*)  d_in[3];
    const float* ew  = (const float*)d_in[4];
    float*       out = (float*)      d_out;

    const int M = in_sizes[0] / D_IN;    // 100000
    const int E = in_sizes[2];           // 3200000

    // 1) zero output
    {
        int n4 = out_size / 4;
        int blocks = (n4 + 255) / 256;
        if (blocks > 8192) blocks = 8192;
        zero_kernel<<<blocks, 256>>>((float4*)out, n4);
    }

    // 2) h = x @ W
    {
        float* h;
        cudaGetSymbolAddress((void**)&h, g_h);
        int blocks = (M + 127) / 128;
        gemm_kernel<<<blocks, 256>>>(x, W, h, M);
    }

    // 3) scatter-add over edges (one warp per edge, 8 warps per block)
    {
        float* h;
        cudaGetSymbolAddress((void**)&h, g_h);
        int blocks = (E + 7) / 8;
        scatter_kernel<<<blocks, 256>>>(h, src, dst, ew, out, E);
    }
}

// round 2
// speedup vs baseline: 1.7323x; 1.7323x over previous
#include <cuda_runtime.h>
#include <cuda_bf16.h>
#include <stdint.h>

// ---------------------------------------------------------------------------
// ConvGraph: out = spmm(A_coo, x @ W)
//   x: [M, 256] f32, W: [256, 128] f32
//   edges: src[E], dst[E] i32, weight[E] f32
//   out[d, :] = sum_{e: dst_e == d} w_e * (x @ W)[src_e, :]
// ---------------------------------------------------------------------------

#define D_IN   256
#define D_OUT  128
#define MAX_M  100000

// scratch for h = x @ W  (51.2 MB, static device array per harness rules)
__device__ float g_h[MAX_M * D_OUT];

// ---------------------------------------------------------------------------
// Kernel 1: zero d_out (it is poisoned to 0xAA before timing)
// ---------------------------------------------------------------------------
__global__ void zero_kernel(float4* out, int n4) {
    int i = blockIdx.x * blockDim.x + threadIdx.x;
    int stride = gridDim.x * blockDim.x;
    for (; i < n4; i += stride)
        out[i] = make_float4(0.f, 0.f, 0.f, 0.f);
}

// ---------------------------------------------------------------------------
// Kernel 2: SGEMM  h[M,128] = x[M,256] @ W[256,128]
// Tile: 128 rows x 128 cols per block, K-chunks of 8. 256 threads,
// each thread computes an 8x8 register micro-tile.
// ---------------------------------------------------------------------------
__global__ __launch_bounds__(256, 2)
void gemm_kernel(const float* __restrict__ x,
                 const float* __restrict__ W,
                 float* __restrict__ h,
                 int M) {
    __shared__ float As[8][128];   // [k][row]
    __shared__ float Bs[8][128];   // [k][col]

    const int row0 = blockIdx.x * 128;
    const int tid  = threadIdx.x;
    const int tx   = tid & 15;        // 0..15 -> col group
    const int ty   = tid >> 4;        // 0..15 -> row group

    float acc[8][8];
#pragma unroll
    for (int i = 0; i < 8; i++)
#pragma unroll
        for (int j = 0; j < 8; j++)
            acc[i][j] = 0.f;

    // A-load mapping: thread t loads float4 at (row = t/2, kc = (t%2)*4)
    const int a_r  = tid >> 1;
    const int a_c4 = (tid & 1) * 4;
    // B-load mapping: thread t loads float4 at (k = t/32, col = (t%32)*4)
    const int b_k  = tid >> 5;
    const int b_c4 = (tid & 31) * 4;

    const bool a_row_ok = (row0 + a_r) < M;

    for (int k0 = 0; k0 < D_IN; k0 += 8) {
        // load A tile 128x8 (transposed into As[k][row])
        float4 av = make_float4(0.f, 0.f, 0.f, 0.f);
        if (a_row_ok)
            av = *reinterpret_cast<const float4*>(
                     &x[(size_t)(row0 + a_r) * D_IN + k0 + a_c4]);
        As[a_c4 + 0][a_r] = av.x;
        As[a_c4 + 1][a_r] = av.y;
        As[a_c4 + 2][a_r] = av.z;
        As[a_c4 + 3][a_r] = av.w;

        // load B tile 8x128
        float4 bv = *reinterpret_cast<const float4*>(
                        &W[(size_t)(k0 + b_k) * D_OUT + b_c4]);
        *reinterpret_cast<float4*>(&Bs[b_k][b_c4]) = bv;

        __syncthreads();

#pragma unroll
        for (int k = 0; k < 8; k++) {
            float a[8], b[8];
#pragma unroll
            for (int i = 0; i < 8; i++) a[i] = As[k][ty * 8 + i];
            float4 b0 = *reinterpret_cast<const float4*>(&Bs[k][tx * 8]);
            float4 b1 = *reinterpret_cast<const float4*>(&Bs[k][tx * 8 + 4]);
            b[0]=b0.x; b[1]=b0.y; b[2]=b0.z; b[3]=b0.w;
            b[4]=b1.x; b[5]=b1.y; b[6]=b1.z; b[7]=b1.w;
#pragma unroll
            for (int i = 0; i < 8; i++)
#pragma unroll
                for (int j = 0; j < 8; j++)
                    acc[i][j] = fmaf(a[i], b[j], acc[i][j]);
        }
        __syncthreads();
    }

    // store 8x8 micro-tile
#pragma unroll
    for (int i = 0; i < 8; i++) {
        int r = row0 + ty * 8 + i;
        if (r < M) {
            float4 v0 = make_float4(acc[i][0], acc[i][1], acc[i][2], acc[i][3]);
            float4 v1 = make_float4(acc[i][4], acc[i][5], acc[i][6], acc[i][7]);
            *reinterpret_cast<float4*>(&h[(size_t)r * D_OUT + tx * 8])     = v0;
            *reinterpret_cast<float4*>(&h[(size_t)r * D_OUT + tx * 8 + 4]) = v1;
        }
    }
}

// ---------------------------------------------------------------------------
// Kernel 3: edge scatter. One warp per edge; each lane handles one float4
// (32 lanes * 16B = 512B = one 128-float row). ONE red.global.add.v4.f32
// per lane (128-bit L2-side reduction) instead of 4 scalar REDs -> 4x fewer
// L2 atomic-ALU ops, which is the measured bottleneck.
// ---------------------------------------------------------------------------
__device__ __forceinline__ void red_add_v4(float* addr, float a, float b,
                                           float c, float d) {
    asm volatile("red.global.add.v4.f32 [%0], {%1, %2, %3, %4};"
                 :: "l"(addr), "f"(a), "f"(b), "f"(c), "f"(d)
                 : "memory");
}

__global__ __launch_bounds__(256)
void scatter_kernel(const float* __restrict__ h,
                    const int*   __restrict__ src,
                    const int*   __restrict__ dst,
                    const float* __restrict__ ew,
                    float*       __restrict__ out,
                    int E) {
    const int warp_id = (blockIdx.x * blockDim.x + threadIdx.x) >> 5;
    const int lane    = threadIdx.x & 31;
    if (warp_id >= E) return;

    int   s, d;
    float w;
    if (lane == 0) {
        s = src[warp_id];
        d = dst[warp_id];
        w = ew[warp_id];
    }
    s = __shfl_sync(0xffffffffu, s, 0);
    d = __shfl_sync(0xffffffffu, d, 0);
    w = __shfl_sync(0xffffffffu, w, 0);

    const float4 v = *reinterpret_cast<const float4*>(
                         &h[(size_t)s * D_OUT + lane * 4]);

    float* o = &out[(size_t)d * D_OUT + lane * 4];
    red_add_v4(o, w * v.x, w * v.y, w * v.z, w * v.w);
}

// ---------------------------------------------------------------------------
extern "C" void kernel_launch(void* const* d_in, const int* in_sizes, int n_in,
                              void* d_out, int out_size) {
    const float* x   = (const float*)d_in[0];
    const float* W   = (const float*)d_in[1];
    const int*   src = (const int*)  d_in[2];
    const int*   dst = (const int*)  d_in[3];
    const float* ew  = (const float*)d_in[4];
    float*       out = (float*)      d_out;

    const int M = in_sizes[0] / D_IN;    // 100000
    const int E = in_sizes[2];           // 3200000

    // 1) zero output
    {
        int n4 = out_size / 4;
        int blocks = (n4 + 255) / 256;
        if (blocks > 8192) blocks = 8192;
        zero_kernel<<<blocks, 256>>>((float4*)out, n4);
    }

    // 2) h = x @ W
    {
        float* h;
        cudaGetSymbolAddress((void**)&h, g_h);
        int blocks = (M + 127) / 128;
        gemm_kernel<<<blocks, 256>>>(x, W, h, M);
    }

    // 3) scatter-add over edges (one warp per edge, 8 warps per block)
    {
        float* h;
        cudaGetSymbolAddress((void**)&h, g_h);
        int blocks = (E + 7) / 8;
        scatter_kernel<<<blocks, 256>>>(h, src, dst, ew, out, E);
    }
}

// round 3
// speedup vs baseline: 2.6543x; 1.5322x over previous
#include <cuda_runtime.h>
#include <cuda_bf16.h>
#include <stdint.h>

#define D_IN   256
#define D_OUT  128
#define MAX_M  100000
#define MAX_E  3200000
#define SCAN_BS 1024
#define MAX_BLKS ((MAX_M + SCAN_BS - 1) / SCAN_BS)   // 98

// scratch (static device arrays per harness rules)
__device__ float g_h[MAX_M * D_OUT];        // h = x @ W (51.2 MB)
__device__ int   g_cnt[MAX_M];              // per-dst degree
__device__ int   g_off[MAX_M + 1];          // exclusive offsets
__device__ int   g_cur[MAX_M];              // fill cursors
__device__ int   g_bsum[MAX_BLKS];          // scan block sums
__device__ int   g_src_r[MAX_E];            // reordered src
__device__ float g_w_r[MAX_E];              // reordered weight

// ---------------------------------------------------------------------------
// 1) zero the degree counters
// ---------------------------------------------------------------------------
__global__ void zero_cnt_kernel(int N) {
    int i = blockIdx.x * blockDim.x + threadIdx.x;
    int stride = gridDim.x * blockDim.x;
    for (; i < N; i += stride) g_cnt[i] = 0;
}

// ---------------------------------------------------------------------------
// 2) histogram of dst
// ---------------------------------------------------------------------------
__global__ void hist_kernel(const int* __restrict__ dst, int E) {
    int i = blockIdx.x * blockDim.x + threadIdx.x;
    int stride = gridDim.x * blockDim.x;
    for (; i < E; i += stride) atomicAdd(&g_cnt[dst[i]], 1);
}

// ---------------------------------------------------------------------------
// 3a) per-block inclusive scan -> exclusive offsets + block totals
// ---------------------------------------------------------------------------
__global__ __launch_bounds__(SCAN_BS)
void scan1_kernel(int N) {
    __shared__ int s[SCAN_BS];
    int t = threadIdx.x;
    int idx = blockIdx.x * SCAN_BS + t;
    int v = (idx < N) ? g_cnt[idx] : 0;
    s[t] = v;
    __syncthreads();
#pragma unroll
    for (int d = 1; d < SCAN_BS; d <<= 1) {
        int x = (t >= d) ? s[t - d] : 0;
        __syncthreads();
        s[t] += x;
        __syncthreads();
    }
    if (idx < N) g_off[idx] = s[t] - v;   // exclusive
    if (t == SCAN_BS - 1) g_bsum[blockIdx.x] = s[t];
}

// ---------------------------------------------------------------------------
// 3b) scan block totals (single thread; <=98 values)
// ---------------------------------------------------------------------------
__global__ void scan2_kernel(int nb) {
    if (threadIdx.x == 0 && blockIdx.x == 0) {
        int run = 0;
        for (int i = 0; i < nb; i++) {
            int v = g_bsum[i];
            g_bsum[i] = run;
            run += v;
        }
    }
}

// ---------------------------------------------------------------------------
// 3c) add block offsets, init cursors, set sentinel
// ---------------------------------------------------------------------------
__global__ void scan3_kernel(int N, int E) {
    int i = blockIdx.x * blockDim.x + threadIdx.x;
    int stride = gridDim.x * blockDim.x;
    for (; i < N; i += stride) {
        int o = g_off[i] + g_bsum[i / SCAN_BS];
        g_off[i] = o;
        g_cur[i] = o;
    }
    if (blockIdx.x == 0 && threadIdx.x == 0) g_off[N] = E;
}

// ---------------------------------------------------------------------------
// 4) bucket edges by dst
// ---------------------------------------------------------------------------
__global__ void reorder_kernel(const int* __restrict__ src,
                               const int* __restrict__ dst,
                               const float* __restrict__ ew,
                               int E) {
    int i = blockIdx.x * blockDim.x + threadIdx.x;
    int stride = gridDim.x * blockDim.x;
    for (; i < E; i += stride) {
        int d = dst[i];
        int p = atomicAdd(&g_cur[d], 1);
        g_src_r[p] = src[i];
        g_w_r[p]   = ew[i];
    }
}

// ---------------------------------------------------------------------------
// 5) SGEMM  h[M,128] = x[M,256] @ W[256,128]
// ---------------------------------------------------------------------------
__global__ __launch_bounds__(256, 2)
void gemm_kernel(const float* __restrict__ x,
                 const float* __restrict__ W,
                 float* __restrict__ h,
                 int M) {
    __shared__ float As[8][128];
    __shared__ float Bs[8][128];

    const int row0 = blockIdx.x * 128;
    const int tid  = threadIdx.x;
    const int tx   = tid & 15;
    const int ty   = tid >> 4;

    float acc[8][8];
#pragma unroll
    for (int i = 0; i < 8; i++)
#pragma unroll
        for (int j = 0; j < 8; j++)
            acc[i][j] = 0.f;

    const int a_r  = tid >> 1;
    const int a_c4 = (tid & 1) * 4;
    const int b_k  = tid >> 5;
    const int b_c4 = (tid & 31) * 4;
    const bool a_row_ok = (row0 + a_r) < M;

    for (int k0 = 0; k0 < D_IN; k0 += 8) {
        float4 av = make_float4(0.f, 0.f, 0.f, 0.f);
        if (a_row_ok)
            av = *reinterpret_cast<const float4*>(
                     &x[(size_t)(row0 + a_r) * D_IN + k0 + a_c4]);
        As[a_c4 + 0][a_r] = av.x;
        As[a_c4 + 1][a_r] = av.y;
        As[a_c4 + 2][a_r] = av.z;
        As[a_c4 + 3][a_r] = av.w;

        float4 bv = *reinterpret_cast<const float4*>(
                        &W[(size_t)(k0 + b_k) * D_OUT + b_c4]);
        *reinterpret_cast<float4*>(&Bs[b_k][b_c4]) = bv;

        __syncthreads();

#pragma unroll
        for (int k = 0; k < 8; k++) {
            float a[8], b[8];
#pragma unroll
            for (int i = 0; i < 8; i++) a[i] = As[k][ty * 8 + i];
            float4 b0 = *reinterpret_cast<const float4*>(&Bs[k][tx * 8]);
            float4 b1 = *reinterpret_cast<const float4*>(&Bs[k][tx * 8 + 4]);
            b[0]=b0.x; b[1]=b0.y; b[2]=b0.z; b[3]=b0.w;
            b[4]=b1.x; b[5]=b1.y; b[6]=b1.z; b[7]=b1.w;
#pragma unroll
            for (int i = 0; i < 8; i++)
#pragma unroll
                for (int j = 0; j < 8; j++)
                    acc[i][j] = fmaf(a[i], b[j], acc[i][j]);
        }
        __syncthreads();
    }

#pragma unroll
    for (int i = 0; i < 8; i++) {
        int r = row0 + ty * 8 + i;
        if (r < M) {
            float4 v0 = make_float4(acc[i][0], acc[i][1], acc[i][2], acc[i][3]);
            float4 v1 = make_float4(acc[i][4], acc[i][5], acc[i][6], acc[i][7]);
            *reinterpret_cast<float4*>(&h[(size_t)r * D_OUT + tx * 8])     = v0;
            *reinterpret_cast<float4*>(&h[(size_t)r * D_OUT + tx * 8 + 4]) = v1;
        }
    }
}

// ---------------------------------------------------------------------------
// 6) gather: one warp per dst node; accumulate in registers, write once.
//    Each lane owns 4 consecutive output floats (float4). Writes every row,
//    including zeros for degree-0 nodes (so no separate out-zeroing pass).
// ---------------------------------------------------------------------------
__global__ __launch_bounds__(256)
void gather_kernel(const float* __restrict__ h,
                   float* __restrict__ out,
                   int N) {
    const int warp_id = (blockIdx.x * blockDim.x + threadIdx.x) >> 5;
    const int lane    = threadIdx.x & 31;
    if (warp_id >= N) return;

    const int beg = g_off[warp_id];
    const int end = g_off[warp_id + 1];

    float4 acc = make_float4(0.f, 0.f, 0.f, 0.f);

    for (int base = beg; base < end; base += 32) {
        const int n = min(32, end - base);
        int   s_l = 0;
        float w_l = 0.f;
        if (lane < n) {
            s_l = g_src_r[base + lane];
            w_l = g_w_r[base + lane];
        }
#pragma unroll 4
        for (int j = 0; j < n; j++) {
            const int   s = __shfl_sync(0xffffffffu, s_l, j);
            const float w = __shfl_sync(0xffffffffu, w_l, j);
            const float4 v = *reinterpret_cast<const float4*>(
                                 &h[(size_t)s * D_OUT + lane * 4]);
            acc.x = fmaf(w, v.x, acc.x);
            acc.y = fmaf(w, v.y, acc.y);
            acc.z = fmaf(w, v.z, acc.z);
            acc.w = fmaf(w, v.w, acc.w);
        }
    }

    *reinterpret_cast<float4*>(&out[(size_t)warp_id * D_OUT + lane * 4]) = acc;
}

// ---------------------------------------------------------------------------
extern "C" void kernel_launch(void* const* d_in, const int* in_sizes, int n_in,
                              void* d_out, int out_size) {
    const float* x   = (const float*)d_in[0];
    const float* W   = (const float*)d_in[1];
    const int*   src = (const int*)  d_in[2];
    const int*   dst = (const int*)  d_in[3];
    const float* ew  = (const float*)d_in[4];
    float*       out = (float*)      d_out;

    const int M = in_sizes[0] / D_IN;    // nodes (100000)
    const int E = in_sizes[2];           // edges (3200000)
    const int N = out_size / D_OUT;      // output nodes (== M)

    float* h;
    cudaGetSymbolAddress((void**)&h, g_h);

    // GEMM first (largest kernel; independent of bucketing)
    gemm_kernel<<<(M + 127) / 128, 256>>>(x, W, h, M);

    // bucketing pipeline
    zero_cnt_kernel<<<128, 256>>>(N);
    hist_kernel<<<512, 256>>>(dst, E);
    const int nb = (N + SCAN_BS - 1) / SCAN_BS;
    scan1_kernel<<<nb, SCAN_BS>>>(N);
    scan2_kernel<<<1, 32>>>(nb);
    scan3_kernel<<<128, 256>>>(N, E);
    reorder_kernel<<<1024, 256>>>(src, dst, ew, E);

    // gather: one warp per node, 8 warps per block
    gather_kernel<<<(N + 7) / 8, 256>>>(h, out, N);
}

// round 4
// speedup vs baseline: 2.7394x; 1.0321x over previous
#include <cuda_runtime.h>
#include <cuda_bf16.h>
#include <stdint.h>

#define D_IN   256
#define D_OUT  128
#define MAX_M  100000
#define MAX_E  3200000
#define SCAN_BS 1024
#define MAX_BLKS ((MAX_M + SCAN_BS - 1) / SCAN_BS)   // 98

// scratch (static device arrays per harness rules)
__device__ float g_h[MAX_M * D_OUT];        // h = x @ W (51.2 MB)
__device__ int   g_cnt[MAX_M];              // per-dst degree
__device__ int   g_off[MAX_M + 1];          // exclusive offsets
__device__ int   g_cur[MAX_M];              // fill cursors
__device__ int   g_bsum[MAX_BLKS];          // scan block sums
__device__ int   g_src_r[MAX_E];            // reordered src
__device__ float g_w_r[MAX_E];              // reordered weight

// ---------------------------------------------------------------------------
// packed f32x2 helpers (FFMA2 — ptxas never emits this from plain C++)
// ---------------------------------------------------------------------------
__device__ __forceinline__ unsigned long long fma2(unsigned long long a,
                                                   unsigned long long b,
                                                   unsigned long long c) {
    unsigned long long d;
    asm("fma.rn.f32x2 %0, %1, %2, %3;" : "=l"(d) : "l"(a), "l"(b), "l"(c));
    return d;
}
__device__ __forceinline__ unsigned long long pack2(float v) {
    unsigned long long d;
    asm("mov.b64 %0, {%1, %2};" : "=l"(d) : "f"(v), "f"(v));
    return d;
}
__device__ __forceinline__ float2 unpack2(unsigned long long v) {
    float lo, hi;
    asm("mov.b64 {%0, %1}, %2;" : "=f"(lo), "=f"(hi) : "l"(v));
    return make_float2(lo, hi);
}

// ---------------------------------------------------------------------------
// 1) zero the degree counters
// ---------------------------------------------------------------------------
__global__ void zero_cnt_kernel(int N) {
    int i = blockIdx.x * blockDim.x + threadIdx.x;
    int stride = gridDim.x * blockDim.x;
    for (; i < N; i += stride) g_cnt[i] = 0;
}

// ---------------------------------------------------------------------------
// 2) histogram of dst
// ---------------------------------------------------------------------------
__global__ void hist_kernel(const int* __restrict__ dst, int E) {
    int i = blockIdx.x * blockDim.x + threadIdx.x;
    int stride = gridDim.x * blockDim.x;
    for (; i < E; i += stride) atomicAdd(&g_cnt[dst[i]], 1);
}

// ---------------------------------------------------------------------------
// 3a) per-block inclusive scan -> exclusive offsets + block totals
// ---------------------------------------------------------------------------
__global__ __launch_bounds__(SCAN_BS)
void scan1_kernel(int N) {
    __shared__ int s[SCAN_BS];
    int t = threadIdx.x;
    int idx = blockIdx.x * SCAN_BS + t;
    int v = (idx < N) ? g_cnt[idx] : 0;
    s[t] = v;
    __syncthreads();
#pragma unroll
    for (int d = 1; d < SCAN_BS; d <<= 1) {
        int x = (t >= d) ? s[t - d] : 0;
        __syncthreads();
        s[t] += x;
        __syncthreads();
    }
    if (idx < N) g_off[idx] = s[t] - v;   // exclusive
    if (t == SCAN_BS - 1) g_bsum[blockIdx.x] = s[t];
}

// ---------------------------------------------------------------------------
// 3b) scan block totals (single thread; <=98 values)
// ---------------------------------------------------------------------------
__global__ void scan2_kernel(int nb) {
    if (threadIdx.x == 0 && blockIdx.x == 0) {
        int run = 0;
        for (int i = 0; i < nb; i++) {
            int v = g_bsum[i];
            g_bsum[i] = run;
            run += v;
        }
    }
}

// ---------------------------------------------------------------------------
// 3c) add block offsets, init cursors, set sentinel
// ---------------------------------------------------------------------------
__global__ void scan3_kernel(int N, int E) {
    int i = blockIdx.x * blockDim.x + threadIdx.x;
    int stride = gridDim.x * blockDim.x;
    for (; i < N; i += stride) {
        int o = g_off[i] + g_bsum[i / SCAN_BS];
        g_off[i] = o;
        g_cur[i] = o;
    }
    if (blockIdx.x == 0 && threadIdx.x == 0) g_off[N] = E;
}

// ---------------------------------------------------------------------------
// 4) bucket edges by dst
// ---------------------------------------------------------------------------
__global__ void reorder_kernel(const int* __restrict__ src,
                               const int* __restrict__ dst,
                               const float* __restrict__ ew,
                               int E) {
    int i = blockIdx.x * blockDim.x + threadIdx.x;
    int stride = gridDim.x * blockDim.x;
    for (; i < E; i += stride) {
        int d = dst[i];
        int p = atomicAdd(&g_cur[d], 1);
        g_src_r[p] = src[i];
        g_w_r[p]   = ew[i];
    }
}

// ---------------------------------------------------------------------------
// 5) SGEMM  h[M,128] = x[M,256] @ W[256,128]
//    8x8 micro-tile per thread, accumulated as 8x4 packed f32x2 (FFMA2):
//    halves the fma-pipe issue count vs scalar FFMA.
// ---------------------------------------------------------------------------
__global__ __launch_bounds__(256, 2)
void gemm_kernel(const float* __restrict__ x,
                 const float* __restrict__ W,
                 float* __restrict__ h,
                 int M) {
    __shared__ float As[8][128];   // [k][row]
    __shared__ float Bs[8][128];   // [k][col]

    const int row0 = blockIdx.x * 128;
    const int tid  = threadIdx.x;
    const int tx   = tid & 15;        // col group
    const int ty   = tid >> 4;        // row group

    unsigned long long acc2[8][4];
#pragma unroll
    for (int i = 0; i < 8; i++)
#pragma unroll
        for (int j = 0; j < 4; j++)
            acc2[i][j] = 0ull;

    const int a_r  = tid >> 1;
    const int a_c4 = (tid & 1) * 4;
    const int b_k  = tid >> 5;
    const int b_c4 = (tid & 31) * 4;
    const bool a_row_ok = (row0 + a_r) < M;

    for (int k0 = 0; k0 < D_IN; k0 += 8) {
        float4 av = make_float4(0.f, 0.f, 0.f, 0.f);
        if (a_row_ok)
            av = *reinterpret_cast<const float4*>(
                     &x[(size_t)(row0 + a_r) * D_IN + k0 + a_c4]);
        As[a_c4 + 0][a_r] = av.x;
        As[a_c4 + 1][a_r] = av.y;
        As[a_c4 + 2][a_r] = av.z;
        As[a_c4 + 3][a_r] = av.w;

        float4 bv = *reinterpret_cast<const float4*>(
                        &W[(size_t)(k0 + b_k) * D_OUT + b_c4]);
        *reinterpret_cast<float4*>(&Bs[b_k][b_c4]) = bv;

        __syncthreads();

#pragma unroll
        for (int k = 0; k < 8; k++) {
            // A: 8 contiguous rows for this thread (2x LDS.128)
            float4 a0 = *reinterpret_cast<const float4*>(&As[k][ty * 8]);
            float4 a1 = *reinterpret_cast<const float4*>(&As[k][ty * 8 + 4]);
            unsigned long long ap[8];
            ap[0] = pack2(a0.x); ap[1] = pack2(a0.y);
            ap[2] = pack2(a0.z); ap[3] = pack2(a0.w);
            ap[4] = pack2(a1.x); ap[5] = pack2(a1.y);
            ap[6] = pack2(a1.z); ap[7] = pack2(a1.w);

            // B: 8 contiguous cols = 4 packed f32x2 (2x LDS.128 as u64 pairs)
            ulonglong2 bb0 = *reinterpret_cast<const ulonglong2*>(&Bs[k][tx * 8]);
            ulonglong2 bb1 = *reinterpret_cast<const ulonglong2*>(&Bs[k][tx * 8 + 4]);

#pragma unroll
            for (int i = 0; i < 8; i++) {
                acc2[i][0] = fma2(ap[i], bb0.x, acc2[i][0]);
                acc2[i][1] = fma2(ap[i], bb0.y, acc2[i][1]);
                acc2[i][2] = fma2(ap[i], bb1.x, acc2[i][2]);
                acc2[i][3] = fma2(ap[i], bb1.y, acc2[i][3]);
            }
        }
        __syncthreads();
    }

#pragma unroll
    for (int i = 0; i < 8; i++) {
        int r = row0 + ty * 8 + i;
        if (r < M) {
            float2 c0 = unpack2(acc2[i][0]);
            float2 c1 = unpack2(acc2[i][1]);
            float2 c2 = unpack2(acc2[i][2]);
            float2 c3 = unpack2(acc2[i][3]);
            float4 v0 = make_float4(c0.x, c0.y, c1.x, c1.y);
            float4 v1 = make_float4(c2.x, c2.y, c3.x, c3.y);
            *reinterpret_cast<float4*>(&h[(size_t)r * D_OUT + tx * 8])     = v0;
            *reinterpret_cast<float4*>(&h[(size_t)r * D_OUT + tx * 8 + 4]) = v1;
        }
    }
}

// ---------------------------------------------------------------------------
// 6) gather: one warp per dst node; accumulate in registers, write once.
// ---------------------------------------------------------------------------
__global__ __launch_bounds__(256)
void gather_kernel(const float* __restrict__ h,
                   float* __restrict__ out,
                   int N) {
    const int warp_id = (blockIdx.x * blockDim.x + threadIdx.x) >> 5;
    const int lane    = threadIdx.x & 31;
    if (warp_id >= N) return;

    const int beg = g_off[warp_id];
    const int end = g_off[warp_id + 1];

    float4 acc = make_float4(0.f, 0.f, 0.f, 0.f);

    for (int base = beg; base < end; base += 32) {
        const int n = min(32, end - base);
        int   s_l = 0;
        float w_l = 0.f;
        if (lane < n) {
            s_l = g_src_r[base + lane];
            w_l = g_w_r[base + lane];
        }
#pragma unroll 4
        for (int j = 0; j < n; j++) {
            const int   s = __shfl_sync(0xffffffffu, s_l, j);
            const float w = __shfl_sync(0xffffffffu, w_l, j);
            const float4 v = *reinterpret_cast<const float4*>(
                                 &h[(size_t)s * D_OUT + lane * 4]);
            acc.x = fmaf(w, v.x, acc.x);
            acc.y = fmaf(w, v.y, acc.y);
            acc.z = fmaf(w, v.z, acc.z);
            acc.w = fmaf(w, v.w, acc.w);
        }
    }

    *reinterpret_cast<float4*>(&out[(size_t)warp_id * D_OUT + lane * 4]) = acc;
}

// ---------------------------------------------------------------------------
extern "C" void kernel_launch(void* const* d_in, const int* in_sizes, int n_in,
                              void* d_out, int out_size) {
    const float* x   = (const float*)d_in[0];
    const float* W   = (const float*)d_in[1];
    const int*   src = (const int*)  d_in[2];
    const int*   dst = (const int*)  d_in[3];
    const float* ew  = (const float*)d_in[4];
    float*       out = (float*)      d_out;

    const int M = in_sizes[0] / D_IN;    // nodes (100000)
    const int E = in_sizes[2];           // edges (3200000)
    const int N = out_size / D_OUT;      // output nodes (== M)

    float* h;
    cudaGetSymbolAddress((void**)&h, g_h);

    // GEMM first (largest kernel; independent of bucketing)
    gemm_kernel<<<(M + 127) / 128, 256>>>(x, W, h, M);

    // bucketing pipeline
    zero_cnt_kernel<<<128, 256>>>(N);
    hist_kernel<<<512, 256>>>(dst, E);
    const int nb = (N + SCAN_BS - 1) / SCAN_BS;
    scan1_kernel<<<nb, SCAN_BS>>>(N);
    scan2_kernel<<<1, 32>>>(nb);
    scan3_kernel<<<128, 256>>>(N, E);
    reorder_kernel<<<1024, 256>>>(src, dst, ew, E);

    // gather: one warp per node, 8 warps per block
    gather_kernel<<<(N + 7) / 8, 256>>>(h, out, N);
}

// round 5
// speedup vs baseline: 3.0756x; 1.1227x over previous
#include <cuda_runtime.h>
#include <cuda_fp16.h>
#include <stdint.h>

#define D_IN   256
#define D_OUT  128
#define MAX_M  100000
#define MAX_E  3200000
#define SCAN_BS 1024
#define MAX_BLKS ((MAX_M + SCAN_BS - 1) / SCAN_BS)   // 98

// scratch (static device arrays per harness rules)
__device__ __half g_h[MAX_M * D_OUT];       // h = x @ W, fp16 (25.6 MB)
__device__ int    g_cnt[MAX_M];             // per-dst degree
__device__ int    g_off[MAX_M + 1];         // exclusive offsets
__device__ int    g_cur[MAX_M];             // fill cursors
__device__ int    g_bsum[MAX_BLKS];         // scan block sums
__device__ int2   g_sw_r[MAX_E];            // reordered {src, w-bits} (25.6 MB)

// ---------------------------------------------------------------------------
// packed f32x2 helpers (FFMA2)
// ---------------------------------------------------------------------------
__device__ __forceinline__ unsigned long long fma2(unsigned long long a,
                                                   unsigned long long b,
                                                   unsigned long long c) {
    unsigned long long d;
    asm("fma.rn.f32x2 %0, %1, %2, %3;" : "=l"(d) : "l"(a), "l"(b), "l"(c));
    return d;
}
__device__ __forceinline__ unsigned long long pack2(float v) {
    unsigned long long d;
    asm("mov.b64 %0, {%1, %2};" : "=l"(d) : "f"(v), "f"(v));
    return d;
}
__device__ __forceinline__ float2 unpack2(unsigned long long v) {
    float lo, hi;
    asm("mov.b64 {%0, %1}, %2;" : "=f"(lo), "=f"(hi) : "l"(v));
    return make_float2(lo, hi);
}

// ---------------------------------------------------------------------------
// 1) zero the degree counters
// ---------------------------------------------------------------------------
__global__ void zero_cnt_kernel(int N) {
    int i = blockIdx.x * blockDim.x + threadIdx.x;
    int stride = gridDim.x * blockDim.x;
    for (; i < N; i += stride) g_cnt[i] = 0;
}

// ---------------------------------------------------------------------------
// 2) histogram of dst
// ---------------------------------------------------------------------------
__global__ void hist_kernel(const int* __restrict__ dst, int E) {
    int i = blockIdx.x * blockDim.x + threadIdx.x;
    int stride = gridDim.x * blockDim.x;
    for (; i < E; i += stride) atomicAdd(&g_cnt[dst[i]], 1);
}

// ---------------------------------------------------------------------------
// 3a) per-block inclusive scan -> exclusive offsets + block totals
// ---------------------------------------------------------------------------
__global__ __launch_bounds__(SCAN_BS)
void scan1_kernel(int N) {
    __shared__ int s[SCAN_BS];
    int t = threadIdx.x;
    int idx = blockIdx.x * SCAN_BS + t;
    int v = (idx < N) ? g_cnt[idx] : 0;
    s[t] = v;
    __syncthreads();
#pragma unroll
    for (int d = 1; d < SCAN_BS; d <<= 1) {
        int x = (t >= d) ? s[t - d] : 0;
        __syncthreads();
        s[t] += x;
        __syncthreads();
    }
    if (idx < N) g_off[idx] = s[t] - v;   // exclusive
    if (t == SCAN_BS - 1) g_bsum[blockIdx.x] = s[t];
}

// ---------------------------------------------------------------------------
// 3b) scan block totals (single thread; <=98 values)
// ---------------------------------------------------------------------------
__global__ void scan2_kernel(int nb) {
    if (threadIdx.x == 0 && blockIdx.x == 0) {
        int run = 0;
        for (int i = 0; i < nb; i++) {
            int v = g_bsum[i];
            g_bsum[i] = run;
            run += v;
        }
    }
}

// ---------------------------------------------------------------------------
// 3c) add block offsets, init cursors, set sentinel
// ---------------------------------------------------------------------------
__global__ void scan3_kernel(int N, int E) {
    int i = blockIdx.x * blockDim.x + threadIdx.x;
    int stride = gridDim.x * blockDim.x;
    for (; i < N; i += stride) {
        int o = g_off[i] + g_bsum[i / SCAN_BS];
        g_off[i] = o;
        g_cur[i] = o;
    }
    if (blockIdx.x == 0 && threadIdx.x == 0) g_off[N] = E;
}

// ---------------------------------------------------------------------------
// 4) bucket edges by dst; pack (src, weight) into one int2 (single STG.64)
// ---------------------------------------------------------------------------
__global__ void reorder_kernel(const int* __restrict__ src,
                               const int* __restrict__ dst,
                               const float* __restrict__ ew,
                               int E) {
    int i = blockIdx.x * blockDim.x + threadIdx.x;
    int stride = gridDim.x * blockDim.x;
    for (; i < E; i += stride) {
        int d = dst[i];
        int p = atomicAdd(&g_cur[d], 1);
        g_sw_r[p] = make_int2(src[i], __float_as_int(ew[i]));
    }
}

// ---------------------------------------------------------------------------
// 5) SGEMM  h[M,128] = x[M,256] @ W[256,128], fp32 accumulate, fp16 store.
//    8x8 micro-tile per thread as 8x4 packed f32x2 (FFMA2).
// ---------------------------------------------------------------------------
__global__ __launch_bounds__(256, 2)
void gemm_kernel(const float* __restrict__ x,
                 const float* __restrict__ W,
                 __half* __restrict__ h,
                 int M) {
    __shared__ float As[8][128];   // [k][row]
    __shared__ float Bs[8][128];   // [k][col]

    const int row0 = blockIdx.x * 128;
    const int tid  = threadIdx.x;
    const int tx   = tid & 15;        // col group
    const int ty   = tid >> 4;        // row group

    unsigned long long acc2[8][4];
#pragma unroll
    for (int i = 0; i < 8; i++)
#pragma unroll
        for (int j = 0; j < 4; j++)
            acc2[i][j] = 0ull;

    const int a_r  = tid >> 1;
    const int a_c4 = (tid & 1) * 4;
    const int b_k  = tid >> 5;
    const int b_c4 = (tid & 31) * 4;
    const bool a_row_ok = (row0 + a_r) < M;

    for (int k0 = 0; k0 < D_IN; k0 += 8) {
        float4 av = make_float4(0.f, 0.f, 0.f, 0.f);
        if (a_row_ok)
            av = *reinterpret_cast<const float4*>(
                     &x[(size_t)(row0 + a_r) * D_IN + k0 + a_c4]);
        As[a_c4 + 0][a_r] = av.x;
        As[a_c4 + 1][a_r] = av.y;
        As[a_c4 + 2][a_r] = av.z;
        As[a_c4 + 3][a_r] = av.w;

        float4 bv = *reinterpret_cast<const float4*>(
                        &W[(size_t)(k0 + b_k) * D_OUT + b_c4]);
        *reinterpret_cast<float4*>(&Bs[b_k][b_c4]) = bv;

        __syncthreads();

#pragma unroll
        for (int k = 0; k < 8; k++) {
            float4 a0 = *reinterpret_cast<const float4*>(&As[k][ty * 8]);
            float4 a1 = *reinterpret_cast<const float4*>(&As[k][ty * 8 + 4]);
            unsigned long long ap[8];
            ap[0] = pack2(a0.x); ap[1] = pack2(a0.y);
            ap[2] = pack2(a0.z); ap[3] = pack2(a0.w);
            ap[4] = pack2(a1.x); ap[5] = pack2(a1.y);
            ap[6] = pack2(a1.z); ap[7] = pack2(a1.w);

            ulonglong2 bb0 = *reinterpret_cast<const ulonglong2*>(&Bs[k][tx * 8]);
            ulonglong2 bb1 = *reinterpret_cast<const ulonglong2*>(&Bs[k][tx * 8 + 4]);

#pragma unroll
            for (int i = 0; i < 8; i++) {
                acc2[i][0] = fma2(ap[i], bb0.x, acc2[i][0]);
                acc2[i][1] = fma2(ap[i], bb0.y, acc2[i][1]);
                acc2[i][2] = fma2(ap[i], bb1.x, acc2[i][2]);
                acc2[i][3] = fma2(ap[i], bb1.y, acc2[i][3]);
            }
        }
        __syncthreads();
    }

    // epilogue: fp32 -> fp16, one 16B store (8 halfs) per row
#pragma unroll
    for (int i = 0; i < 8; i++) {
        int r = row0 + ty * 8 + i;
        if (r < M) {
            float2 c0 = unpack2(acc2[i][0]);
            float2 c1 = unpack2(acc2[i][1]);
            float2 c2 = unpack2(acc2[i][2]);
            float2 c3 = unpack2(acc2[i][3]);
            __half2 p0 = __floats2half2_rn(c0.x, c0.y);
            __half2 p1 = __floats2half2_rn(c1.x, c1.y);
            __half2 p2 = __floats2half2_rn(c2.x, c2.y);
            __half2 p3 = __floats2half2_rn(c3.x, c3.y);
            uint4 v;
            v.x = *reinterpret_cast<unsigned*>(&p0);
            v.y = *reinterpret_cast<unsigned*>(&p1);
            v.z = *reinterpret_cast<unsigned*>(&p2);
            v.w = *reinterpret_cast<unsigned*>(&p3);
            *reinterpret_cast<uint4*>(&h[(size_t)r * D_OUT + tx * 8]) = v;
        }
    }
}

// ---------------------------------------------------------------------------
// 6) gather: one warp per dst node; fp16 h rows (256B each), fp32 accumulate,
//    write each output row exactly once. Lane owns 4 consecutive outputs.
// ---------------------------------------------------------------------------
__global__ __launch_bounds__(256)
void gather_kernel(const __half* __restrict__ h,
                   float* __restrict__ out,
                   int N) {
    const int warp_id = (blockIdx.x * blockDim.x + threadIdx.x) >> 5;
    const int lane    = threadIdx.x & 31;
    if (warp_id >= N) return;

    const int beg = g_off[warp_id];
    const int end = g_off[warp_id + 1];

    float4 acc = make_float4(0.f, 0.f, 0.f, 0.f);

    for (int base = beg; base < end; base += 32) {
        const int n = min(32, end - base);
        int2 sw = make_int2(0, 0);
        if (lane < n) sw = g_sw_r[base + lane];

#pragma unroll 4
        for (int j = 0; j < n; j++) {
            const int   s = __shfl_sync(0xffffffffu, sw.x, j);
            const float w = __int_as_float(__shfl_sync(0xffffffffu, sw.y, j));
            // 4 halfs (8B) per lane = one LDG.64; warp covers the 256B row
            const uint2 raw = *reinterpret_cast<const uint2*>(
                                  &h[(size_t)s * D_OUT + lane * 4]);
            const float2 f0 = __half22float2(*reinterpret_cast<const __half2*>(&raw.x));
            const float2 f1 = __half22float2(*reinterpret_cast<const __half2*>(&raw.y));
            acc.x = fmaf(w, f0.x, acc.x);
            acc.y = fmaf(w, f0.y, acc.y);
            acc.z = fmaf(w, f1.x, acc.z);
            acc.w = fmaf(w, f1.y, acc.w);
        }
    }

    *reinterpret_cast<float4*>(&out[(size_t)warp_id * D_OUT + lane * 4]) = acc;
}

// ---------------------------------------------------------------------------
extern "C" void kernel_launch(void* const* d_in, const int* in_sizes, int n_in,
                              void* d_out, int out_size) {
    const float* x   = (const float*)d_in[0];
    const float* W   = (const float*)d_in[1];
    const int*   src = (const int*)  d_in[2];
    const int*   dst = (const int*)  d_in[3];
    const float* ew  = (const float*)d_in[4];
    float*       out = (float*)      d_out;

    const int M = in_sizes[0] / D_IN;    // nodes (100000)
    const int E = in_sizes[2];           // edges (3200000)
    const int N = out_size / D_OUT;      // output nodes (== M)

    __half* h;
    cudaGetSymbolAddress((void**)&h, g_h);

    // bucketing pipeline first, GEMM placed 6th (for ncu slot visibility)
    zero_cnt_kernel<<<128, 256>>>(N);
    hist_kernel<<<512, 256>>>(dst, E);
    const int nb = (N + SCAN_BS - 1) / SCAN_BS;
    scan1_kernel<<<nb, SCAN_BS>>>(N);
    scan2_kernel<<<1, 32>>>(nb);
    scan3_kernel<<<128, 256>>>(N, E);
    gemm_kernel<<<(M + 127) / 128, 256>>>(x, W, h, M);
    reorder_kernel<<<1024, 256>>>(src, dst, ew, E);

    // gather: one warp per node, 8 warps per block
    gather_kernel<<<(N + 7) / 8, 256>>>(h, out, N);
}

// round 6
// speedup vs baseline: 4.6653x; 1.5169x over previous
#include <cuda_runtime.h>
#include <cuda_fp16.h>
#include <mma.h>
#include <stdint.h>

using namespace nvcuda;

#define D_IN   256
#define D_OUT  128
#define MAX_M  100000
#define MAX_E  3200000
#define SCAN_BS 1024
#define MAX_BLKS ((MAX_M + SCAN_BS - 1) / SCAN_BS)   // 98

// scratch (static device arrays per harness rules)
__device__ __half g_h[MAX_M * D_OUT];       // h = x @ W, fp16 (25.6 MB)
__device__ int    g_cnt[MAX_M];             // per-dst degree
__device__ int    g_off[MAX_M + 1];         // exclusive offsets
__device__ int    g_cur[MAX_M];             // fill cursors
__device__ int    g_bsum[MAX_BLKS];         // scan block sums
__device__ int2   g_sw_r[MAX_E];            // reordered {src, w-bits}

// ---------------------------------------------------------------------------
// 1) zero the degree counters
// ---------------------------------------------------------------------------
__global__ void zero_cnt_kernel(int N) {
    int i = blockIdx.x * blockDim.x + threadIdx.x;
    int stride = gridDim.x * blockDim.x;
    for (; i < N; i += stride) g_cnt[i] = 0;
}

// ---------------------------------------------------------------------------
// 2) histogram of dst
// ---------------------------------------------------------------------------
__global__ void hist_kernel(const int* __restrict__ dst, int E) {
    int i = blockIdx.x * blockDim.x + threadIdx.x;
    int stride = gridDim.x * blockDim.x;
    for (; i < E; i += stride) atomicAdd(&g_cnt[dst[i]], 1);
}

// ---------------------------------------------------------------------------
// 3a) per-block inclusive scan -> exclusive offsets + block totals
// ---------------------------------------------------------------------------
__global__ __launch_bounds__(SCAN_BS)
void scan1_kernel(int N) {
    __shared__ int s[SCAN_BS];
    int t = threadIdx.x;
    int idx = blockIdx.x * SCAN_BS + t;
    int v = (idx < N) ? g_cnt[idx] : 0;
    s[t] = v;
    __syncthreads();
#pragma unroll
    for (int d = 1; d < SCAN_BS; d <<= 1) {
        int x = (t >= d) ? s[t - d] : 0;
        __syncthreads();
        s[t] += x;
        __syncthreads();
    }
    if (idx < N) g_off[idx] = s[t] - v;   // exclusive
    if (t == SCAN_BS - 1) g_bsum[blockIdx.x] = s[t];
}

// ---------------------------------------------------------------------------
// 3b) scan block totals (one block, shared-memory scan; nb <= 98 < 128)
// ---------------------------------------------------------------------------
__global__ __launch_bounds__(128)
void scan2_kernel(int nb) {
    __shared__ int s[128];
    int t = threadIdx.x;
    int v = (t < nb) ? g_bsum[t] : 0;
    s[t] = v;
    __syncthreads();
#pragma unroll
    for (int d = 1; d < 128; d <<= 1) {
        int x = (t >= d) ? s[t - d] : 0;
        __syncthreads();
        s[t] += x;
        __syncthreads();
    }
    if (t < nb) g_bsum[t] = s[t] - v;     // exclusive
}

// ---------------------------------------------------------------------------
// 3c) add block offsets, init cursors, set sentinel
// ---------------------------------------------------------------------------
__global__ void scan3_kernel(int N, int E) {
    int i = blockIdx.x * blockDim.x + threadIdx.x;
    int stride = gridDim.x * blockDim.x;
    for (; i < N; i += stride) {
        int o = g_off[i] + g_bsum[i / SCAN_BS];
        g_off[i] = o;
        g_cur[i] = o;
    }
    if (blockIdx.x == 0 && threadIdx.x == 0) g_off[N] = E;
}

// ---------------------------------------------------------------------------
// 4) bucket edges by dst; pack (src, weight) into one int2
// ---------------------------------------------------------------------------
__global__ void reorder_kernel(const int* __restrict__ src,
                               const int* __restrict__ dst,
                               const float* __restrict__ ew,
                               int E) {
    int i = blockIdx.x * blockDim.x + threadIdx.x;
    int stride = gridDim.x * blockDim.x;
    for (; i < E; i += stride) {
        int d = dst[i];
        int p = atomicAdd(&g_cur[d], 1);
        g_sw_r[p] = make_int2(src[i], __float_as_int(ew[i]));
    }
}

// ---------------------------------------------------------------------------
// 5) Tensor-core GEMM: h[M,128] = fp16(x) @ fp16(W), fp32 accumulate,
//    fp16 store. Block = 128 rows x 128 cols, 8 warps; each warp owns a
//    16x128 strip (8 wmma 16x16x16 accumulators). K consumed in chunks of 16.
// ---------------------------------------------------------------------------
#define AS_STRIDE 24    // halfs per A row (16 + 8 pad); mult of 8
#define BS_STRIDE 136   // halfs per B row (128 + 8 pad); mult of 8

__global__ __launch_bounds__(256, 2)
void gemm_tc_kernel(const float* __restrict__ x,
                    const float* __restrict__ W,
                    __half* __restrict__ h,
                    int M) {
    __shared__ __half As[128 * AS_STRIDE];          // 6.0 KB
    __shared__ __half Bs[16 * BS_STRIDE];           // 4.25 KB
    __shared__ float  Ep[8][16 * 16];               // 8 KB epilogue patches

    const int row0 = blockIdx.x * 128;
    const int tid  = threadIdx.x;
    const int w    = tid >> 5;        // warp 0..7
    const int lane = tid & 31;

    wmma::fragment<wmma::accumulator, 16, 16, 16, float> acc[8];
#pragma unroll
    for (int j = 0; j < 8; j++) wmma::fill_fragment(acc[j], 0.0f);

    // A-load mapping: thread t -> row = t/2, k-offset = (t%2)*8
    const int a_r   = tid >> 1;
    const int a_off = (tid & 1) * 8;
    const bool a_ok = (row0 + a_r) < M;
    // B-load mapping: thread t -> k = t/16, col = (t%16)*8
    const int b_k   = tid >> 4;
    const int b_c   = (tid & 15) * 8;

    for (int k0 = 0; k0 < D_IN; k0 += 16) {
        // A chunk: 128 rows x 16 k, fp32 -> fp16
        {
            float4 v0 = make_float4(0.f,0.f,0.f,0.f);
            float4 v1 = v0;
            if (a_ok) {
                const float* p = &x[(size_t)(row0 + a_r) * D_IN + k0 + a_off];
                v0 = *reinterpret_cast<const float4*>(p);
                v1 = *reinterpret_cast<const float4*>(p + 4);
            }
            __half2 h0 = __floats2half2_rn(v0.x, v0.y);
            __half2 h1 = __floats2half2_rn(v0.z, v0.w);
            __half2 h2 = __floats2half2_rn(v1.x, v1.y);
            __half2 h3 = __floats2half2_rn(v1.z, v1.w);
            uint4 packed;
            packed.x = *reinterpret_cast<unsigned*>(&h0);
            packed.y = *reinterpret_cast<unsigned*>(&h1);
            packed.z = *reinterpret_cast<unsigned*>(&h2);
            packed.w = *reinterpret_cast<unsigned*>(&h3);
            *reinterpret_cast<uint4*>(&As[a_r * AS_STRIDE + a_off]) = packed;
        }
        // B chunk: 16 k x 128 cols, fp32 -> fp16
        {
            const float* p = &W[(size_t)(k0 + b_k) * D_OUT + b_c];
            float4 v0 = *reinterpret_cast<const float4*>(p);
            float4 v1 = *reinterpret_cast<const float4*>(p + 4);
            __half2 h0 = __floats2half2_rn(v0.x, v0.y);
            __half2 h1 = __floats2half2_rn(v0.z, v0.w);
            __half2 h2 = __floats2half2_rn(v1.x, v1.y);
            __half2 h3 = __floats2half2_rn(v1.z, v1.w);
            uint4 packed;
            packed.x = *reinterpret_cast<unsigned*>(&h0);
            packed.y = *reinterpret_cast<unsigned*>(&h1);
            packed.z = *reinterpret_cast<unsigned*>(&h2);
            packed.w = *reinterpret_cast<unsigned*>(&h3);
            *reinterpret_cast<uint4*>(&Bs[b_k * BS_STRIDE + b_c]) = packed;
        }
        __syncthreads();

        wmma::fragment<wmma::matrix_a, 16, 16, 16, __half, wmma::row_major> af;
        wmma::load_matrix_sync(af, &As[(w * 16) * AS_STRIDE], AS_STRIDE);
#pragma unroll
        for (int j = 0; j < 8; j++) {
            wmma::fragment<wmma::matrix_b, 16, 16, 16, __half, wmma::row_major> bf;
            wmma::load_matrix_sync(bf, &Bs[j * 16], BS_STRIDE);
            wmma::mma_sync(acc[j], af, bf, acc[j]);
        }
        __syncthreads();
    }

    // epilogue: per warp, stage each 16x16 f32 tile in smem, convert to fp16
    const int e_r = lane >> 1;            // 0..15
    const int e_c = (lane & 1) * 8;       // 0 or 8
    const int grow = row0 + w * 16 + e_r;
#pragma unroll
    for (int j = 0; j < 8; j++) {
        wmma::store_matrix_sync(&Ep[w][0], acc[j], 16, wmma::mem_row_major);
        __syncwarp();
        if (grow < M) {
            const float* q = &Ep[w][e_r * 16 + e_c];
            __half2 p0 = __floats2half2_rn(q[0], q[1]);
            __half2 p1 = __floats2half2_rn(q[2], q[3]);
            __half2 p2 = __floats2half2_rn(q[4], q[5]);
            __half2 p3 = __floats2half2_rn(q[6], q[7]);
            uint4 v;
            v.x = *reinterpret_cast<unsigned*>(&p0);
            v.y = *reinterpret_cast<unsigned*>(&p1);
            v.z = *reinterpret_cast<unsigned*>(&p2);
            v.w = *reinterpret_cast<unsigned*>(&p3);
            *reinterpret_cast<uint4*>(&h[(size_t)grow * D_OUT + j * 16 + e_c]) = v;
        }
        __syncwarp();
    }
}

// ---------------------------------------------------------------------------
// 6) gather: one warp per dst node; fp16 h rows, fp32 accumulate,
//    one float4 store per lane.
// ---------------------------------------------------------------------------
__global__ __launch_bounds__(256)
void gather_kernel(const __half* __restrict__ h,
                   float* __restrict__ out,
                   int N) {
    const int warp_id = (blockIdx.x * blockDim.x + threadIdx.x) >> 5;
    const int lane    = threadIdx.x & 31;
    if (warp_id >= N) return;

    const int beg = g_off[warp_id];
    const int end = g_off[warp_id + 1];

    float4 acc = make_float4(0.f, 0.f, 0.f, 0.f);

    for (int base = beg; base < end; base += 32) {
        const int n = min(32, end - base);
        int2 sw = make_int2(0, 0);
        if (lane < n) sw = g_sw_r[base + lane];

#pragma unroll 4
        for (int j = 0; j < n; j++) {
            const int   s = __shfl_sync(0xffffffffu, sw.x, j);
            const float w = __int_as_float(__shfl_sync(0xffffffffu, sw.y, j));
            const uint2 raw = *reinterpret_cast<const uint2*>(
                                  &h[(size_t)s * D_OUT + lane * 4]);
            const float2 f0 = __half22float2(*reinterpret_cast<const __half2*>(&raw.x));
            const float2 f1 = __half22float2(*reinterpret_cast<const __half2*>(&raw.y));
            acc.x = fmaf(w, f0.x, acc.x);
            acc.y = fmaf(w, f0.y, acc.y);
            acc.z = fmaf(w, f1.x, acc.z);
            acc.w = fmaf(w, f1.y, acc.w);
        }
    }

    *reinterpret_cast<float4*>(&out[(size_t)warp_id * D_OUT + lane * 4]) = acc;
}

// ---------------------------------------------------------------------------
extern "C" void kernel_launch(void* const* d_in, const int* in_sizes, int n_in,
                              void* d_out, int out_size) {
    const float* x   = (const float*)d_in[0];
    const float* W   = (const float*)d_in[1];
    const int*   src = (const int*)  d_in[2];
    const int*   dst = (const int*)  d_in[3];
    const float* ew  = (const float*)d_in[4];
    float*       out = (float*)      d_out;

    const int M = in_sizes[0] / D_IN;    // nodes (100000)
    const int E = in_sizes[2];           // edges (3200000)
    const int N = out_size / D_OUT;      // output nodes (== M)

    __half* h;
    cudaGetSymbolAddress((void**)&h, g_h);

    zero_cnt_kernel<<<128, 256>>>(N);
    hist_kernel<<<512, 256>>>(dst, E);
    const int nb = (N + SCAN_BS - 1) / SCAN_BS;
    scan1_kernel<<<nb, SCAN_BS>>>(N);
    scan2_kernel<<<1, 128>>>(nb);
    scan3_kernel<<<128, 256>>>(N, E);
    gemm_tc_kernel<<<(M + 127) / 128, 256>>>(x, W, h, M);   // 6th launch: ncu slot
    reorder_kernel<<<1024, 256>>>(src, dst, ew, E);

    gather_kernel<<<(N + 7) / 8, 256>>>(h, out, N);
}

// round 7
// speedup vs baseline: 4.8440x; 1.0383x over previous
#include <cuda_runtime.h>
#include <cuda_fp16.h>
#include <mma.h>
#include <stdint.h>

using namespace nvcuda;

#define D_IN   256
#define D_OUT  128
#define MAX_M  100000
#define MAX_E  3200000
#define SCAN_BS 1024

// scratch (static device arrays per harness rules)
__device__ __half g_h[MAX_M * D_OUT];       // h = x @ W, fp16 (25.6 MB)
__device__ int    g_cnt[MAX_M];             // per-dst degree
__device__ int    g_off[MAX_M];             // bucket start offsets
__device__ int    g_cur[MAX_M];             // fill cursors
__device__ int    g_total;                  // running bucket-base counter
__device__ int2   g_sw_r[MAX_E];            // reordered {src, w-bits}

// ---------------------------------------------------------------------------
// 1) zero degree counters + global total
// ---------------------------------------------------------------------------
__global__ void zero_cnt_kernel(int N) {
    int i = blockIdx.x * blockDim.x + threadIdx.x;
    int stride = gridDim.x * blockDim.x;
    for (; i < N; i += stride) g_cnt[i] = 0;
    if (blockIdx.x == 0 && threadIdx.x == 0) g_total = 0;
}

// ---------------------------------------------------------------------------
// 2) histogram of dst
// ---------------------------------------------------------------------------
__global__ void hist_kernel(const int* __restrict__ dst, int E) {
    int i = blockIdx.x * blockDim.x + threadIdx.x;
    int stride = gridDim.x * blockDim.x;
    for (; i < E; i += stride) atomicAdd(&g_cnt[dst[i]], 1);
}

// ---------------------------------------------------------------------------
// 3) single-kernel offset assignment: block-local scan + one atomicAdd per
//    block to claim a contiguous range. Bucket order across blocks is
//    run-varying; results identical up to fp summation order.
// ---------------------------------------------------------------------------
__global__ __launch_bounds__(SCAN_BS)
void scan_assign_kernel(int N) {
    __shared__ int s[SCAN_BS];
    __shared__ int base_sh;
    int t = threadIdx.x;
    int idx = blockIdx.x * SCAN_BS + t;
    int v = (idx < N) ? g_cnt[idx] : 0;
    s[t] = v;
    __syncthreads();
#pragma unroll
    for (int d = 1; d < SCAN_BS; d <<= 1) {
        int x = (t >= d) ? s[t - d] : 0;
        __syncthreads();
        s[t] += x;
        __syncthreads();
    }
    if (t == SCAN_BS - 1) base_sh = atomicAdd(&g_total, s[t]);
    __syncthreads();
    if (idx < N) {
        int o = base_sh + s[t] - v;
        g_off[idx] = o;
        g_cur[idx] = o;
    }
}

// ---------------------------------------------------------------------------
// 4) bucket edges by dst; pack (src, weight) into one int2
// ---------------------------------------------------------------------------
__global__ void reorder_kernel(const int* __restrict__ src,
                               const int* __restrict__ dst,
                               const float* __restrict__ ew,
                               int E) {
    int i = blockIdx.x * blockDim.x + threadIdx.x;
    int stride = gridDim.x * blockDim.x;
    for (; i < E; i += stride) {
        int d = dst[i];
        int p = atomicAdd(&g_cur[d], 1);
        g_sw_r[p] = make_int2(src[i], __float_as_int(ew[i]));
    }
}

// ---------------------------------------------------------------------------
// 5) Tensor-core GEMM: h[M,128] = fp16(x) @ fp16(W), fp32 accumulate,
//    fp16 store. Block = 128x128, 8 warps; warp owns a 16x128 strip.
// ---------------------------------------------------------------------------
#define AS_STRIDE 24    // halfs per A row (16 + 8 pad)
#define BS_STRIDE 136   // halfs per B row (128 + 8 pad)

__global__ __launch_bounds__(256, 2)
void gemm_tc_kernel(const float* __restrict__ x,
                    const float* __restrict__ W,
                    __half* __restrict__ h,
                    int M) {
    __shared__ __half As[128 * AS_STRIDE];
    __shared__ __half Bs[16 * BS_STRIDE];
    __shared__ float  Ep[8][16 * 16];

    const int row0 = blockIdx.x * 128;
    const int tid  = threadIdx.x;
    const int w    = tid >> 5;
    const int lane = tid & 31;

    wmma::fragment<wmma::accumulator, 16, 16, 16, float> acc[8];
#pragma unroll
    for (int j = 0; j < 8; j++) wmma::fill_fragment(acc[j], 0.0f);

    const int a_r   = tid >> 1;
    const int a_off = (tid & 1) * 8;
    const bool a_ok = (row0 + a_r) < M;
    const int b_k   = tid >> 4;
    const int b_c   = (tid & 15) * 8;

    for (int k0 = 0; k0 < D_IN; k0 += 16) {
        {
            float4 v0 = make_float4(0.f,0.f,0.f,0.f);
            float4 v1 = v0;
            if (a_ok) {
                const float* p = &x[(size_t)(row0 + a_r) * D_IN + k0 + a_off];
                v0 = *reinterpret_cast<const float4*>(p);
                v1 = *reinterpret_cast<const float4*>(p + 4);
            }
            __half2 h0 = __floats2half2_rn(v0.x, v0.y);
            __half2 h1 = __floats2half2_rn(v0.z, v0.w);
            __half2 h2 = __floats2half2_rn(v1.x, v1.y);
            __half2 h3 = __floats2half2_rn(v1.z, v1.w);
            uint4 packed;
            packed.x = *reinterpret_cast<unsigned*>(&h0);
            packed.y = *reinterpret_cast<unsigned*>(&h1);
            packed.z = *reinterpret_cast<unsigned*>(&h2);
            packed.w = *reinterpret_cast<unsigned*>(&h3);
            *reinterpret_cast<uint4*>(&As[a_r * AS_STRIDE + a_off]) = packed;
        }
        {
            const float* p = &W[(size_t)(k0 + b_k) * D_OUT + b_c];
            float4 v0 = *reinterpret_cast<const float4*>(p);
            float4 v1 = *reinterpret_cast<const float4*>(p + 4);
            __half2 h0 = __floats2half2_rn(v0.x, v0.y);
            __half2 h1 = __floats2half2_rn(v0.z, v0.w);
            __half2 h2 = __floats2half2_rn(v1.x, v1.y);
            __half2 h3 = __floats2half2_rn(v1.z, v1.w);
            uint4 packed;
            packed.x = *reinterpret_cast<unsigned*>(&h0);
            packed.y = *reinterpret_cast<unsigned*>(&h1);
            packed.z = *reinterpret_cast<unsigned*>(&h2);
            packed.w = *reinterpret_cast<unsigned*>(&h3);
            *reinterpret_cast<uint4*>(&Bs[b_k * BS_STRIDE + b_c]) = packed;
        }
        __syncthreads();

        wmma::fragment<wmma::matrix_a, 16, 16, 16, __half, wmma::row_major> af;
        wmma::load_matrix_sync(af, &As[(w * 16) * AS_STRIDE], AS_STRIDE);
#pragma unroll
        for (int j = 0; j < 8; j++) {
            wmma::fragment<wmma::matrix_b, 16, 16, 16, __half, wmma::row_major> bf;
            wmma::load_matrix_sync(bf, &Bs[j * 16], BS_STRIDE);
            wmma::mma_sync(acc[j], af, bf, acc[j]);
        }
        __syncthreads();
    }

    const int e_r = lane >> 1;
    const int e_c = (lane & 1) * 8;
    const int grow = row0 + w * 16 + e_r;
#pragma unroll
    for (int j = 0; j < 8; j++) {
        wmma::store_matrix_sync(&Ep[w][0], acc[j], 16, wmma::mem_row_major);
        __syncwarp();
        if (grow < M) {
            const float* q = &Ep[w][e_r * 16 + e_c];
            __half2 p0 = __floats2half2_rn(q[0], q[1]);
            __half2 p1 = __floats2half2_rn(q[2], q[3]);
            __half2 p2 = __floats2half2_rn(q[4], q[5]);
            __half2 p3 = __floats2half2_rn(q[6], q[7]);
            uint4 v;
            v.x = *reinterpret_cast<unsigned*>(&p0);
            v.y = *reinterpret_cast<unsigned*>(&p1);
            v.z = *reinterpret_cast<unsigned*>(&p2);
            v.w = *reinterpret_cast<unsigned*>(&p3);
            *reinterpret_cast<uint4*>(&h[(size_t)grow * D_OUT + j * 16 + e_c]) = v;
        }
        __syncwarp();
    }
}

// ---------------------------------------------------------------------------
// 6) gather: one warp per dst node; fp16 h rows, fp32 accumulate.
//    end = off + cnt (buckets no longer globally ordered).
// ---------------------------------------------------------------------------
__global__ __launch_bounds__(256)
void gather_kernel(const __half* __restrict__ h,
                   float* __restrict__ out,
                   int N) {
    const int warp_id = (blockIdx.x * blockDim.x + threadIdx.x) >> 5;
    const int lane    = threadIdx.x & 31;
    if (warp_id >= N) return;

    const int beg = g_off[warp_id];
    const int end = beg + g_cnt[warp_id];

    float4 acc = make_float4(0.f, 0.f, 0.f, 0.f);

    for (int base = beg; base < end; base += 32) {
        const int n = min(32, end - base);
        int2 sw = make_int2(0, 0);
        if (lane < n) sw = g_sw_r[base + lane];

#pragma unroll 4
        for (int j = 0; j < n; j++) {
            const int   s = __shfl_sync(0xffffffffu, sw.x, j);
            const float w = __int_as_float(__shfl_sync(0xffffffffu, sw.y, j));
            const uint2 raw = *reinterpret_cast<const uint2*>(
                                  &h[(size_t)s * D_OUT + lane * 4]);
            const float2 f0 = __half22float2(*reinterpret_cast<const __half2*>(&raw.x));
            const float2 f1 = __half22float2(*reinterpret_cast<const __half2*>(&raw.y));
            acc.x = fmaf(w, f0.x, acc.x);
            acc.y = fmaf(w, f0.y, acc.y);
            acc.z = fmaf(w, f1.x, acc.z);
            acc.w = fmaf(w, f1.y, acc.w);
        }
    }

    *reinterpret_cast<float4*>(&out[(size_t)warp_id * D_OUT + lane * 4]) = acc;
}

// ---------------------------------------------------------------------------
extern "C" void kernel_launch(void* const* d_in, const int* in_sizes, int n_in,
                              void* d_out, int out_size) {
    const float* x   = (const float*)d_in[0];
    const float* W   = (const float*)d_in[1];
    const int*   src = (const int*)  d_in[2];
    const int*   dst = (const int*)  d_in[3];
    const float* ew  = (const float*)d_in[4];
    float*       out = (float*)      d_out;

    const int M = in_sizes[0] / D_IN;    // nodes (100000)
    const int E = in_sizes[2];           // edges (3200000)
    const int N = out_size / D_OUT;      // output nodes (== M)

    __half* h;
    cudaGetSymbolAddress((void**)&h, g_h);

    // persistent side stream + fork/join events (created once; same work
    // is enqueued on every call, so launches remain deterministic)
    static cudaStream_t s_side = nullptr;
    static cudaEvent_t  ev_fork = nullptr, ev_join = nullptr;
    if (s_side == nullptr) {
        cudaStreamCreateWithFlags(&s_side, cudaStreamNonBlocking);
        cudaEventCreateWithFlags(&ev_fork, cudaEventDisableTiming);
        cudaEventCreateWithFlags(&ev_join, cudaEventDisableTiming);
    }

    // fork: GEMM is independent of the bucketing chain
    cudaEventRecord(ev_fork, 0);
    cudaStreamWaitEvent(s_side, ev_fork, 0);
    gemm_tc_kernel<<<(M + 127) / 128, 256, 0, s_side>>>(x, W, h, M);
    cudaEventRecord(ev_join, s_side);

    // main stream: bucketing chain
    zero_cnt_kernel<<<128, 256>>>(N);
    hist_kernel<<<512, 256>>>(dst, E);
    scan_assign_kernel<<<(N + SCAN_BS - 1) / SCAN_BS, SCAN_BS>>>(N);
    reorder_kernel<<<1024, 256>>>(src, dst, ew, E);

    // join, then gather
    cudaStreamWaitEvent(0, ev_join, 0);
    gather_kernel<<<(N + 7) / 8, 256>>>(h, out, N);
}

// round 8
// speedup vs baseline: 5.0123x; 1.0348x over previous
#include <cuda_runtime.h>
#include <cuda_fp16.h>
#include <mma.h>
#include <stdint.h>

using namespace nvcuda;

#define D_IN   256
#define D_OUT  128
#define MAX_M  100000
#define MAX_E  3200000
#define SCAN_BS 1024

// scratch (static device arrays per harness rules)
__device__ __half g_h[MAX_M * D_OUT];       // h = x @ W, fp16 (25.6 MB)
__device__ int    g_cnt[MAX_M];             // per-dst degree
__device__ int    g_off[MAX_M];             // bucket start offsets
__device__ int    g_cur[MAX_M];             // fill cursors
__device__ int    g_total;                  // running bucket-base counter
__device__ int2   g_sw_r[MAX_E];            // reordered {src, w-bits}

// ---------------------------------------------------------------------------
// 1) zero degree counters + global total
// ---------------------------------------------------------------------------
__global__ void zero_cnt_kernel(int N) {
    int i = blockIdx.x * blockDim.x + threadIdx.x;
    int stride = gridDim.x * blockDim.x;
    for (; i < N; i += stride) g_cnt[i] = 0;
    if (blockIdx.x == 0 && threadIdx.x == 0) g_total = 0;
}

// ---------------------------------------------------------------------------
// 2) histogram of dst (int4-vectorized reads: 4 edges per iteration)
// ---------------------------------------------------------------------------
__global__ void hist_kernel(const int* __restrict__ dst, int E) {
    int i = blockIdx.x * blockDim.x + threadIdx.x;
    int stride = gridDim.x * blockDim.x;
    const int E4 = E >> 2;
    const int4* dst4 = reinterpret_cast<const int4*>(dst);
    for (int j = i; j < E4; j += stride) {
        int4 d = dst4[j];
        atomicAdd(&g_cnt[d.x], 1);
        atomicAdd(&g_cnt[d.y], 1);
        atomicAdd(&g_cnt[d.z], 1);
        atomicAdd(&g_cnt[d.w], 1);
    }
    // tail
    for (int j = E4 * 4 + i; j < E; j += stride) atomicAdd(&g_cnt[dst[j]], 1);
}

// ---------------------------------------------------------------------------
// 3) single-kernel offset assignment: block-local scan + one atomicAdd per
//    block to claim a contiguous range.
// ---------------------------------------------------------------------------
__global__ __launch_bounds__(SCAN_BS)
void scan_assign_kernel(int N) {
    __shared__ int s[SCAN_BS];
    __shared__ int base_sh;
    int t = threadIdx.x;
    int idx = blockIdx.x * SCAN_BS + t;
    int v = (idx < N) ? g_cnt[idx] : 0;
    s[t] = v;
    __syncthreads();
#pragma unroll
    for (int d = 1; d < SCAN_BS; d <<= 1) {
        int x = (t >= d) ? s[t - d] : 0;
        __syncthreads();
        s[t] += x;
        __syncthreads();
    }
    if (t == SCAN_BS - 1) base_sh = atomicAdd(&g_total, s[t]);
    __syncthreads();
    if (idx < N) {
        int o = base_sh + s[t] - v;
        g_off[idx] = o;
        g_cur[idx] = o;
    }
}

// ---------------------------------------------------------------------------
// 4) bucket edges by dst; pack (src, weight) into one int2
// ---------------------------------------------------------------------------
__global__ void reorder_kernel(const int* __restrict__ src,
                               const int* __restrict__ dst,
                               const float* __restrict__ ew,
                               int E) {
    int i = blockIdx.x * blockDim.x + threadIdx.x;
    int stride = gridDim.x * blockDim.x;
    for (; i < E; i += stride) {
        int d = dst[i];
        int p = atomicAdd(&g_cur[d], 1);
        g_sw_r[p] = make_int2(src[i], __float_as_int(ew[i]));
    }
}

// ---------------------------------------------------------------------------
// 5) Tensor-core GEMM: h[M,128] = fp16(x) @ fp16(W), fp32 accumulate,
//    fp16 store. Block = 128x128, 8 warps; warp owns a 16x128 strip.
// ---------------------------------------------------------------------------
#define AS_STRIDE 24    // halfs per A row (16 + 8 pad)
#define BS_STRIDE 136   // halfs per B row (128 + 8 pad)

__global__ __launch_bounds__(256, 2)
void gemm_tc_kernel(const float* __restrict__ x,
                    const float* __restrict__ W,
                    __half* __restrict__ h,
                    int M) {
    __shared__ __half As[128 * AS_STRIDE];
    __shared__ __half Bs[16 * BS_STRIDE];
    __shared__ float  Ep[8][16 * 16];

    const int row0 = blockIdx.x * 128;
    const int tid  = threadIdx.x;
    const int w    = tid >> 5;
    const int lane = tid & 31;

    wmma::fragment<wmma::accumulator, 16, 16, 16, float> acc[8];
#pragma unroll
    for (int j = 0; j < 8; j++) wmma::fill_fragment(acc[j], 0.0f);

    const int a_r   = tid >> 1;
    const int a_off = (tid & 1) * 8;
    const bool a_ok = (row0 + a_r) < M;
    const int b_k   = tid >> 4;
    const int b_c   = (tid & 15) * 8;

    for (int k0 = 0; k0 < D_IN; k0 += 16) {
        {
            float4 v0 = make_float4(0.f,0.f,0.f,0.f);
            float4 v1 = v0;
            if (a_ok) {
                const float* p = &x[(size_t)(row0 + a_r) * D_IN + k0 + a_off];
                v0 = *reinterpret_cast<const float4*>(p);
                v1 = *reinterpret_cast<const float4*>(p + 4);
            }
            __half2 h0 = __floats2half2_rn(v0.x, v0.y);
            __half2 h1 = __floats2half2_rn(v0.z, v0.w);
            __half2 h2 = __floats2half2_rn(v1.x, v1.y);
            __half2 h3 = __floats2half2_rn(v1.z, v1.w);
            uint4 packed;
            packed.x = *reinterpret_cast<unsigned*>(&h0);
            packed.y = *reinterpret_cast<unsigned*>(&h1);
            packed.z = *reinterpret_cast<unsigned*>(&h2);
            packed.w = *reinterpret_cast<unsigned*>(&h3);
            *reinterpret_cast<uint4*>(&As[a_r * AS_STRIDE + a_off]) = packed;
        }
        {
            const float* p = &W[(size_t)(k0 + b_k) * D_OUT + b_c];
            float4 v0 = *reinterpret_cast<const float4*>(p);
            float4 v1 = *reinterpret_cast<const float4*>(p + 4);
            __half2 h0 = __floats2half2_rn(v0.x, v0.y);
            __half2 h1 = __floats2half2_rn(v0.z, v0.w);
            __half2 h2 = __floats2half2_rn(v1.x, v1.y);
            __half2 h3 = __floats2half2_rn(v1.z, v1.w);
            uint4 packed;
            packed.x = *reinterpret_cast<unsigned*>(&h0);
            packed.y = *reinterpret_cast<unsigned*>(&h1);
            packed.z = *reinterpret_cast<unsigned*>(&h2);
            packed.w = *reinterpret_cast<unsigned*>(&h3);
            *reinterpret_cast<uint4*>(&Bs[b_k * BS_STRIDE + b_c]) = packed;
        }
        __syncthreads();

        wmma::fragment<wmma::matrix_a, 16, 16, 16, __half, wmma::row_major> af;
        wmma::load_matrix_sync(af, &As[(w * 16) * AS_STRIDE], AS_STRIDE);
#pragma unroll
        for (int j = 0; j < 8; j++) {
            wmma::fragment<wmma::matrix_b, 16, 16, 16, __half, wmma::row_major> bf;
            wmma::load_matrix_sync(bf, &Bs[j * 16], BS_STRIDE);
            wmma::mma_sync(acc[j], af, bf, acc[j]);
        }
        __syncthreads();
    }

    const int e_r = lane >> 1;
    const int e_c = (lane & 1) * 8;
    const int grow = row0 + w * 16 + e_r;
#pragma unroll
    for (int j = 0; j < 8; j++) {
        wmma::store_matrix_sync(&Ep[w][0], acc[j], 16, wmma::mem_row_major);
        __syncwarp();
        if (grow < M) {
            const float* q = &Ep[w][e_r * 16 + e_c];
            __half2 p0 = __floats2half2_rn(q[0], q[1]);
            __half2 p1 = __floats2half2_rn(q[2], q[3]);
            __half2 p2 = __floats2half2_rn(q[4], q[5]);
            __half2 p3 = __floats2half2_rn(q[6], q[7]);
            uint4 v;
            v.x = *reinterpret_cast<unsigned*>(&p0);
            v.y = *reinterpret_cast<unsigned*>(&p1);
            v.z = *reinterpret_cast<unsigned*>(&p2);
            v.w = *reinterpret_cast<unsigned*>(&p3);
            *reinterpret_cast<uint4*>(&h[(size_t)grow * D_OUT + j * 16 + e_c]) = v;
        }
        __syncwarp();
    }
}

// ---------------------------------------------------------------------------
// 6) gather: one warp per dst node, TWO edges in flight per iteration.
//    Half-warp h (0/1) handles edge j+h; each of its 16 lanes loads uint4
//    (8 halfs = 8 features). Final cross-half shfl combine; lanes 0-15 store.
// ---------------------------------------------------------------------------
__global__ __launch_bounds__(256)
void gather_kernel(const __half* __restrict__ h,
                   float* __restrict__ out,
                   int N) {
    const int warp_id = (blockIdx.x * blockDim.x + threadIdx.x) >> 5;
    const int lane    = threadIdx.x & 31;
    if (warp_id >= N) return;

    const int half_id = lane >> 4;        // 0 or 1
    const int lid16   = lane & 15;        // feature group: [lid16*8, lid16*8+8)

    const int beg = g_off[warp_id];
    const int end = beg + g_cnt[warp_id];

    float acc[8];
#pragma unroll
    for (int k = 0; k < 8; k++) acc[k] = 0.f;

    for (int base = beg; base < end; base += 32) {
        const int n = min(32, end - base);
        // lanes >= n hold (src=0, w=0): safe dummy for odd-n overread
        int2 sw = make_int2(0, 0);
        if (lane < n) sw = g_sw_r[base + lane];

#pragma unroll 4
        for (int j = 0; j < n; j += 2) {
            const int jj = j + half_id;                       // <= 31 always
            const int   s = __shfl_sync(0xffffffffu, sw.x, jj);
            const float w = __int_as_float(__shfl_sync(0xffffffffu, sw.y, jj));
            // 16B load: 8 consecutive halfs of row s
            const uint4 raw = *reinterpret_cast<const uint4*>(
                                  &h[(size_t)s * D_OUT + lid16 * 8]);
            const float2 f0 = __half22float2(*reinterpret_cast<const __half2*>(&raw.x));
            const float2 f1 = __half22float2(*reinterpret_cast<const __half2*>(&raw.y));
            const float2 f2 = __half22float2(*reinterpret_cast<const __half2*>(&raw.z));
            const float2 f3 = __half22float2(*reinterpret_cast<const __half2*>(&raw.w));
            acc[0] = fmaf(w, f0.x, acc[0]);
            acc[1] = fmaf(w, f0.y, acc[1]);
            acc[2] = fmaf(w, f1.x, acc[2]);
            acc[3] = fmaf(w, f1.y, acc[3]);
            acc[4] = fmaf(w, f2.x, acc[4]);
            acc[5] = fmaf(w, f2.y, acc[5]);
            acc[6] = fmaf(w, f3.x, acc[6]);
            acc[7] = fmaf(w, f3.y, acc[7]);
        }
    }

    // combine the two half-warps (features are identical per lid16)
#pragma unroll
    for (int k = 0; k < 8; k++)
        acc[k] += __shfl_down_sync(0xffffffffu, acc[k], 16);

    if (lane < 16) {
        float* o = &out[(size_t)warp_id * D_OUT + lid16 * 8];
        *reinterpret_cast<float4*>(o)     = make_float4(acc[0], acc[1], acc[2], acc[3]);
        *reinterpret_cast<float4*>(o + 4) = make_float4(acc[4], acc[5], acc[6], acc[7]);
    }
}

// ---------------------------------------------------------------------------
extern "C" void kernel_launch(void* const* d_in, const int* in_sizes, int n_in,
                              void* d_out, int out_size) {
    const float* x   = (const float*)d_in[0];
    const float* W   = (const float*)d_in[1];
    const int*   src = (const int*)  d_in[2];
    const int*   dst = (const int*)  d_in[3];
    const float* ew  = (const float*)d_in[4];
    float*       out = (float*)      d_out;

    const int M = in_sizes[0] / D_IN;    // nodes (100000)
    const int E = in_sizes[2];           // edges (3200000)
    const int N = out_size / D_OUT;      // output nodes (== M)

    __half* h;
    cudaGetSymbolAddress((void**)&h, g_h);

    static cudaStream_t s_side = nullptr;
    static cudaEvent_t  ev_fork = nullptr, ev_join = nullptr;
    if (s_side == nullptr) {
        cudaStreamCreateWithFlags(&s_side, cudaStreamNonBlocking);
        cudaEventCreateWithFlags(&ev_fork, cudaEventDisableTiming);
        cudaEventCreateWithFlags(&ev_join, cudaEventDisableTiming);
    }

    // fork: GEMM is independent of the bucketing chain
    cudaEventRecord(ev_fork, 0);
    cudaStreamWaitEvent(s_side, ev_fork, 0);
    gemm_tc_kernel<<<(M + 127) / 128, 256, 0, s_side>>>(x, W, h, M);
    cudaEventRecord(ev_join, s_side);

    // main stream: bucketing chain
    zero_cnt_kernel<<<128, 256>>>(N);
    hist_kernel<<<512, 256>>>(dst, E);
    scan_assign_kernel<<<(N + SCAN_BS - 1) / SCAN_BS, SCAN_BS>>>(N);
    reorder_kernel<<<2048, 256>>>(src, dst, ew, E);

    // join, then gather
    cudaStreamWaitEvent(0, ev_join, 0);
    gather_kernel<<<(N + 7) / 8, 256>>>(h, out, N);
}

// round 9
// speedup vs baseline: 5.0797x; 1.0134x over previous
#include <cuda_runtime.h>
#include <cuda_fp16.h>
#include <mma.h>
#include <stdint.h>

using namespace nvcuda;

#define D_IN   256
#define D_OUT  128
#define MAX_M  100000
#define MAX_E  3200000
#define SCAN_BS 1024

// scratch (static device arrays per harness rules)
__device__ __half g_h[MAX_M * D_OUT];       // h = x @ W, fp16 (25.6 MB)
__device__ int    g_cnt[MAX_M];             // per-dst degree
__device__ int    g_off[MAX_M];             // bucket start offsets
__device__ int    g_rank[MAX_E];            // per-edge rank within its bucket
__device__ int    g_total;                  // running bucket-base counter
__device__ int2   g_sw_r[MAX_E];            // reordered {src, w-bits}

// ---------------------------------------------------------------------------
// 1) zero degree counters + global total
// ---------------------------------------------------------------------------
__global__ void zero_cnt_kernel(int N) {
    int i = blockIdx.x * blockDim.x + threadIdx.x;
    int stride = gridDim.x * blockDim.x;
    for (; i < N; i += stride) g_cnt[i] = 0;
    if (blockIdx.x == 0 && threadIdx.x == 0) g_total = 0;
}

// ---------------------------------------------------------------------------
// 2) histogram of dst + per-edge rank (the atomic's return value IS the rank;
//    this removes all atomics from the scatter pass)
// ---------------------------------------------------------------------------
__global__ void hist_rank_kernel(const int* __restrict__ dst, int E) {
    int i = blockIdx.x * blockDim.x + threadIdx.x;
    int stride = gridDim.x * blockDim.x;
    const int E4 = E >> 2;
    const int4* dst4 = reinterpret_cast<const int4*>(dst);
    for (int j = i; j < E4; j += stride) {
        int4 d = dst4[j];
        int4 r;
        r.x = atomicAdd(&g_cnt[d.x], 1);
        r.y = atomicAdd(&g_cnt[d.y], 1);
        r.z = atomicAdd(&g_cnt[d.z], 1);
        r.w = atomicAdd(&g_cnt[d.w], 1);
        reinterpret_cast<int4*>(g_rank)[j] = r;   // coalesced
    }
    for (int j = E4 * 4 + i; j < E; j += stride)
        g_rank[j] = atomicAdd(&g_cnt[dst[j]], 1);
}

// ---------------------------------------------------------------------------
// 3) single-kernel offset assignment: block-local scan + one atomicAdd per
//    block to claim a contiguous range.
// ---------------------------------------------------------------------------
__global__ __launch_bounds__(SCAN_BS)
void scan_assign_kernel(int N) {
    __shared__ int s[SCAN_BS];
    __shared__ int base_sh;
    int t = threadIdx.x;
    int idx = blockIdx.x * SCAN_BS + t;
    int v = (idx < N) ? g_cnt[idx] : 0;
    s[t] = v;
    __syncthreads();
#pragma unroll
    for (int d = 1; d < SCAN_BS; d <<= 1) {
        int x = (t >= d) ? s[t - d] : 0;
        __syncthreads();
        s[t] += x;
        __syncthreads();
    }
    if (t == SCAN_BS - 1) base_sh = atomicAdd(&g_total, s[t]);
    __syncthreads();
    if (idx < N) g_off[idx] = base_sh + s[t] - v;
}

// ---------------------------------------------------------------------------
// 4) scatter edges into buckets — atomic-free: p = off[dst] + rank.
//    off[] is 400KB (L2-resident) so the random reads are cheap.
// ---------------------------------------------------------------------------
__global__ void reorder_kernel(const int* __restrict__ src,
                               const int* __restrict__ dst,
                               const float* __restrict__ ew,
                               int E) {
    int i = blockIdx.x * blockDim.x + threadIdx.x;
    int stride = gridDim.x * blockDim.x;
    for (; i < E; i += stride) {
        int d = dst[i];
        int p = g_off[d] + g_rank[i];
        g_sw_r[p] = make_int2(src[i], __float_as_int(ew[i]));
    }
}

// ---------------------------------------------------------------------------
// 5) Tensor-core GEMM: h[M,128] = fp16(x) @ fp16(W), fp32 accumulate,
//    fp16 store. Block = 128x128, 8 warps; warp owns a 16x128 strip.
// ---------------------------------------------------------------------------
#define AS_STRIDE 24    // halfs per A row (16 + 8 pad)
#define BS_STRIDE 136   // halfs per B row (128 + 8 pad)

__global__ __launch_bounds__(256, 2)
void gemm_tc_kernel(const float* __restrict__ x,
                    const float* __restrict__ W,
                    __half* __restrict__ h,
                    int M) {
    __shared__ __half As[128 * AS_STRIDE];
    __shared__ __half Bs[16 * BS_STRIDE];
    __shared__ float  Ep[8][16 * 16];

    const int row0 = blockIdx.x * 128;
    const int tid  = threadIdx.x;
    const int w    = tid >> 5;
    const int lane = tid & 31;

    wmma::fragment<wmma::accumulator, 16, 16, 16, float> acc[8];
#pragma unroll
    for (int j = 0; j < 8; j++) wmma::fill_fragment(acc[j], 0.0f);

    const int a_r   = tid >> 1;
    const int a_off = (tid & 1) * 8;
    const bool a_ok = (row0 + a_r) < M;
    const int b_k   = tid >> 4;
    const int b_c   = (tid & 15) * 8;

    for (int k0 = 0; k0 < D_IN; k0 += 16) {
        {
            float4 v0 = make_float4(0.f,0.f,0.f,0.f);
            float4 v1 = v0;
            if (a_ok) {
                const float* p = &x[(size_t)(row0 + a_r) * D_IN + k0 + a_off];
                v0 = *reinterpret_cast<const float4*>(p);
                v1 = *reinterpret_cast<const float4*>(p + 4);
            }
            __half2 h0 = __floats2half2_rn(v0.x, v0.y);
            __half2 h1 = __floats2half2_rn(v0.z, v0.w);
            __half2 h2 = __floats2half2_rn(v1.x, v1.y);
            __half2 h3 = __floats2half2_rn(v1.z, v1.w);
            uint4 packed;
            packed.x = *reinterpret_cast<unsigned*>(&h0);
            packed.y = *reinterpret_cast<unsigned*>(&h1);
            packed.z = *reinterpret_cast<unsigned*>(&h2);
            packed.w = *reinterpret_cast<unsigned*>(&h3);
            *reinterpret_cast<uint4*>(&As[a_r * AS_STRIDE + a_off]) = packed;
        }
        {
            const float* p = &W[(size_t)(k0 + b_k) * D_OUT + b_c];
            float4 v0 = *reinterpret_cast<const float4*>(p);
            float4 v1 = *reinterpret_cast<const float4*>(p + 4);
            __half2 h0 = __floats2half2_rn(v0.x, v0.y);
            __half2 h1 = __floats2half2_rn(v0.z, v0.w);
            __half2 h2 = __floats2half2_rn(v1.x, v1.y);
            __half2 h3 = __floats2half2_rn(v1.z, v1.w);
            uint4 packed;
            packed.x = *reinterpret_cast<unsigned*>(&h0);
            packed.y = *reinterpret_cast<unsigned*>(&h1);
            packed.z = *reinterpret_cast<unsigned*>(&h2);
            packed.w = *reinterpret_cast<unsigned*>(&h3);
            *reinterpret_cast<uint4*>(&Bs[b_k * BS_STRIDE + b_c]) = packed;
        }
        __syncthreads();

        wmma::fragment<wmma::matrix_a, 16, 16, 16, __half, wmma::row_major> af;
        wmma::load_matrix_sync(af, &As[(w * 16) * AS_STRIDE], AS_STRIDE);
#pragma unroll
        for (int j = 0; j < 8; j++) {
            wmma::fragment<wmma::matrix_b, 16, 16, 16, __half, wmma::row_major> bf;
            wmma::load_matrix_sync(bf, &Bs[j * 16], BS_STRIDE);
            wmma::mma_sync(acc[j], af, bf, acc[j]);
        }
        __syncthreads();
    }

    const int e_r = lane >> 1;
    const int e_c = (lane & 1) * 8;
    const int grow = row0 + w * 16 + e_r;
#pragma unroll
    for (int j = 0; j < 8; j++) {
        wmma::store_matrix_sync(&Ep[w][0], acc[j], 16, wmma::mem_row_major);
        __syncwarp();
        if (grow < M) {
            const float* q = &Ep[w][e_r * 16 + e_c];
            __half2 p0 = __floats2half2_rn(q[0], q[1]);
            __half2 p1 = __floats2half2_rn(q[2], q[3]);
            __half2 p2 = __floats2half2_rn(q[4], q[5]);
            __half2 p3 = __floats2half2_rn(q[6], q[7]);
            uint4 v;
            v.x = *reinterpret_cast<unsigned*>(&p0);
            v.y = *reinterpret_cast<unsigned*>(&p1);
            v.z = *reinterpret_cast<unsigned*>(&p2);
            v.w = *reinterpret_cast<unsigned*>(&p3);
            *reinterpret_cast<uint4*>(&h[(size_t)grow * D_OUT + j * 16 + e_c]) = v;
        }
        __syncwarp();
    }
}

// ---------------------------------------------------------------------------
// 6) gather: one warp per dst node, two edges in flight per iteration.
//    Half-warp handles edge j+half; 16 lanes x uint4 (8 halfs) each.
// ---------------------------------------------------------------------------
__global__ __launch_bounds__(256)
void gather_kernel(const __half* __restrict__ h,
                   float* __restrict__ out,
                   int N) {
    const int warp_id = (blockIdx.x * blockDim.x + threadIdx.x) >> 5;
    const int lane    = threadIdx.x & 31;
    if (warp_id >= N) return;

    const int half_id = lane >> 4;
    const int lid16   = lane & 15;

    const int beg = g_off[warp_id];
    const int end = beg + g_cnt[warp_id];

    float acc[8];
#pragma unroll
    for (int k = 0; k < 8; k++) acc[k] = 0.f;

    for (int base = beg; base < end; base += 32) {
        const int n = min(32, end - base);
        int2 sw = make_int2(0, 0);
        if (lane < n) sw = g_sw_r[base + lane];

#pragma unroll 4
        for (int j = 0; j < n; j += 2) {
            const int jj = j + half_id;
            const int   s = __shfl_sync(0xffffffffu, sw.x, jj);
            const float w = __int_as_float(__shfl_sync(0xffffffffu, sw.y, jj));
            const uint4 raw = *reinterpret_cast<const uint4*>(
                                  &h[(size_t)s * D_OUT + lid16 * 8]);
            const float2 f0 = __half22float2(*reinterpret_cast<const __half2*>(&raw.x));
            const float2 f1 = __half22float2(*reinterpret_cast<const __half2*>(&raw.y));
            const float2 f2 = __half22float2(*reinterpret_cast<const __half2*>(&raw.z));
            const float2 f3 = __half22float2(*reinterpret_cast<const __half2*>(&raw.w));
            acc[0] = fmaf(w, f0.x, acc[0]);
            acc[1] = fmaf(w, f0.y, acc[1]);
            acc[2] = fmaf(w, f1.x, acc[2]);
            acc[3] = fmaf(w, f1.y, acc[3]);
            acc[4] = fmaf(w, f2.x, acc[4]);
            acc[5] = fmaf(w, f2.y, acc[5]);
            acc[6] = fmaf(w, f3.x, acc[6]);
            acc[7] = fmaf(w, f3.y, acc[7]);
        }
    }

#pragma unroll
    for (int k = 0; k < 8; k++)
        acc[k] += __shfl_down_sync(0xffffffffu, acc[k], 16);

    if (lane < 16) {
        float* o = &out[(size_t)warp_id * D_OUT + lid16 * 8];
        *reinterpret_cast<float4*>(o)     = make_float4(acc[0], acc[1], acc[2], acc[3]);
        *reinterpret_cast<float4*>(o + 4) = make_float4(acc[4], acc[5], acc[6], acc[7]);
    }
}

// ---------------------------------------------------------------------------
extern "C" void kernel_launch(void* const* d_in, const int* in_sizes, int n_in,
                              void* d_out, int out_size) {
    const float* x   = (const float*)d_in[0];
    const float* W   = (const float*)d_in[1];
    const int*   src = (const int*)  d_in[2];
    const int*   dst = (const int*)  d_in[3];
    const float* ew  = (const float*)d_in[4];
    float*       out = (float*)      d_out;

    const int M = in_sizes[0] / D_IN;    // nodes (100000)
    const int E = in_sizes[2];           // edges (3200000)
    const int N = out_size / D_OUT;      // output nodes (== M)

    __half* h;
    cudaGetSymbolAddress((void**)&h, g_h);

    static cudaStream_t s_side = nullptr;
    static cudaEvent_t  ev_fork = nullptr, ev_join = nullptr;
    if (s_side == nullptr) {
        cudaStreamCreateWithFlags(&s_side, cudaStreamNonBlocking);
        cudaEventCreateWithFlags(&ev_fork, cudaEventDisableTiming);
        cudaEventCreateWithFlags(&ev_join, cudaEventDisableTiming);
    }

    // fork: GEMM is independent of the bucketing chain
    cudaEventRecord(ev_fork, 0);
    cudaStreamWaitEvent(s_side, ev_fork, 0);
    gemm_tc_kernel<<<(M + 127) / 128, 256, 0, s_side>>>(x, W, h, M);
    cudaEventRecord(ev_join, s_side);

    // main stream: bucketing chain (scatter pass is now atomic-free)
    zero_cnt_kernel<<<128, 256>>>(N);
    hist_rank_kernel<<<1024, 256>>>(dst, E);
    scan_assign_kernel<<<(N + SCAN_BS - 1) / SCAN_BS, SCAN_BS>>>(N);
    reorder_kernel<<<2048, 256>>>(src, dst, ew, E);

    // join, then gather
    cudaStreamWaitEvent(0, ev_join, 0);
    gather_kernel<<<(N + 7) / 8, 256>>>(h, out, N);
}